// round 7
// baseline (speedup 1.0000x reference)
#include <cuda_runtime.h>
#include <cuda_fp16.h>
#include <cstdint>

#define N_NODES 50000
#define N_EDGES 1600000
#define N_GRAPHS 2048
#define D 133
#define DP 136           // fp32 padded row (floats)
#define DPH 144          // fp16 padded row (halves) = 288B
#define EPSV 1e-5f
#define SCAN_B 1024
#define SCAN_NB ((N_NODES + SCAN_B - 1) / SCAN_B)   // 49

// -------- scratch (static device globals; no runtime allocation) --------
__device__ __align__(16) __half g_A16[(size_t)N_NODES * DPH];  // gemm out, dinv-scaled, fp16
__device__ __align__(16) float  g_C[(size_t)N_NODES * DP];     // gather out / layer-2 input
__device__ __align__(16) float  g_P[(size_t)N_GRAPHS * DP];    // pool accumulator
__device__ float g_dinv[N_NODES];
__device__ int   g_cnt[N_NODES];
__device__ int   g_off[N_NODES + 1];
__device__ int   g_cursor[N_NODES];
__device__ int   g_csr[N_EDGES];
__device__ int   g_bsum[SCAN_NB];
__device__ int   g_cntg[N_GRAPHS];
__device__ float g_post1[3 * DP];    // bias | s | t   (zero-padded)
__device__ float g_post2[3 * DP];

// ------------------------------------------------------------------
__global__ void zero_fused_kernel() {
    int i = blockIdx.x * blockDim.x + threadIdx.x;
    if (i < N_GRAPHS * DP) g_P[i] = 0.0f;
    if (i < N_NODES)       g_cnt[i] = 0;
}

__global__ void count_deg_kernel(const int* __restrict__ ei) {
    int e = blockIdx.x * blockDim.x + threadIdx.x;
    if (e < N_EDGES) atomicAdd(&g_cnt[__ldg(&ei[N_EDGES + e])], 1);
}

__global__ void dinv_kernel() {
    int i = blockIdx.x * blockDim.x + threadIdx.x;
    if (i < N_NODES) g_dinv[i] = rsqrtf((float)(g_cnt[i] + 1));   // +1 self-loop
}

// ---- 3-kernel exclusive scan of g_cnt -> g_off ----
__global__ void scan1_kernel() {
    __shared__ int sh[SCAN_B];
    int t = threadIdx.x;
    int i = blockIdx.x * SCAN_B + t;
    int v = (i < N_NODES) ? g_cnt[i] : 0;
    sh[t] = v;
    __syncthreads();
#pragma unroll
    for (int d = 1; d < SCAN_B; d <<= 1) {
        int x = (t >= d) ? sh[t - d] : 0;
        __syncthreads();
        sh[t] += x;
        __syncthreads();
    }
    if (i < N_NODES) g_off[i] = sh[t] - v;           // exclusive, local
    if (t == SCAN_B - 1) g_bsum[blockIdx.x] = sh[t];
}

__global__ void scan2_kernel() {
    if (threadIdx.x == 0) {
        int acc = 0;
        for (int b = 0; b < SCAN_NB; b++) {
            int v = g_bsum[b];
            g_bsum[b] = acc;
            acc += v;
        }
    }
}

__global__ void scan3_kernel() {
    int i = blockIdx.x * blockDim.x + threadIdx.x;
    if (i < N_NODES) {
        int o = g_off[i] + g_bsum[i / SCAN_B];
        g_off[i] = o;
        g_cursor[i] = o;
    }
    if (i == 0) g_off[N_NODES] = N_EDGES;
}

__global__ void fill_csr_kernel(const int* __restrict__ ei) {
    int e = blockIdx.x * blockDim.x + threadIdx.x;
    if (e < N_EDGES) {
        int r = __ldg(&ei[e]);
        int c = __ldg(&ei[N_EDGES + e]);
        int pos = atomicAdd(&g_cursor[c], 1);
        g_csr[pos] = r;
    }
}

// ---- per-layer fused BN constants: bias | s | t, zero-padded to DP ----
__global__ void prep_post_kernel(const float* __restrict__ bias, const float* __restrict__ gam,
                                 const float* __restrict__ beta, const float* __restrict__ rm,
                                 const float* __restrict__ rv, float* __restrict__ dst) {
    int c = threadIdx.x;
    if (c >= DP) return;
    float bb = 0.0f, ss = 0.0f, tt = 0.0f;
    if (c < D) {
        bb = bias[c];
        float sc = gam[c] * rsqrtf(rv[c] + EPSV);
        ss = sc;
        tt = beta[c] - rm[c] * sc;
    }
    dst[c] = bb; dst[DP + c] = ss; dst[2 * DP + c] = tt;
}

// ------------------------------------------------------------------
__device__ __forceinline__ uint32_t f2tf32(float f) {
    uint32_t r;
    asm("cvt.rna.tf32.f32 %0, %1;" : "=r"(r) : "f"(f));
    return r;
}

__device__ __forceinline__ void mma_tf32(float* d,
                                         uint32_t a0, uint32_t a1, uint32_t a2, uint32_t a3,
                                         uint32_t b0, uint32_t b1) {
    asm volatile("mma.sync.aligned.m16n8k8.row.col.f32.tf32.tf32.f32 "
                 "{%0,%1,%2,%3}, {%4,%5,%6,%7}, {%8,%9}, {%0,%1,%2,%3};"
                 : "+f"(d[0]), "+f"(d[1]), "+f"(d[2]), "+f"(d[3])
                 : "r"(a0), "r"(a1), "r"(a2), "r"(a3), "r"(b0), "r"(b1));
}

// Tensor-core GEMM: g_A16[row] = fp16( dinv[row] * (X @ W) ), pads zeroed.
// smem = W only (74 KB tf32) -> 3 blocks/SM. A-frags loaded directly from
// global (each element consumed once). 8 warps x 16 rows = 128 rows/block.
__global__ __launch_bounds__(256)
void gemm_tc_kernel(const float* __restrict__ X, int ldx,
                    const float* __restrict__ W) {
    extern __shared__ uint32_t ws[];         // [136][136] tf32 bits, zero-padded

    int tid  = threadIdx.x;
    int w    = tid >> 5;
    int lane = tid & 31;

    // one-pass W fill (convert + zero-pad), unrolled for MLP
#pragma unroll 8
    for (int i = tid; i < 136 * 136; i += 256) {
        int k = i / 136, n = i - k * 136;
        ws[i] = (k < D && n < D) ? f2tf32(__ldg(&W[k * D + n])) : 0u;
    }
    __syncthreads();

    const int r0 = lane >> 2;        // A row group / B n
    const int kc = lane & 3;         // A k within quad / B k
    int rowbase = (blockIdx.x * 8 + w) * 16;
    int row0 = rowbase + r0;
    int row1 = row0 + 8;
    bool v0 = row0 < N_NODES;
    bool v1 = row1 < N_NODES;
    const float* X0 = X + (size_t)row0 * ldx;
    const float* X1 = X + (size_t)row1 * ldx;

    float acc[17][4];
#pragma unroll
    for (int nt = 0; nt < 17; nt++)
#pragma unroll
        for (int q = 0; q < 4; q++) acc[nt][q] = 0.0f;

#pragma unroll 4
    for (int ks = 0; ks < 17; ks++) {
        int c0 = ks * 8 + kc;
        int c1 = c0 + 4;
        uint32_t a0 = (v0 && c0 < D) ? f2tf32(__ldg(X0 + c0)) : 0u;
        uint32_t a1 = (v1 && c0 < D) ? f2tf32(__ldg(X1 + c0)) : 0u;
        uint32_t a2 = (v0 && c1 < D) ? f2tf32(__ldg(X0 + c1)) : 0u;
        uint32_t a3 = (v1 && c1 < D) ? f2tf32(__ldg(X1 + c1)) : 0u;
        const uint32_t* wr0 = ws + (ks * 8 + kc) * 136 + r0;   // bk=kc, bn=r0
        const uint32_t* wr1 = wr0 + 4 * 136;
#pragma unroll
        for (int nt = 0; nt < 17; nt++) {
            mma_tf32(acc[nt], a0, a1, a2, a3, wr0[nt * 8], wr1[nt * 8]);
        }
    }

    // epilogue: dinv scale -> fp16 half2 stores; D frag rows (r0, r0+8), cols nt*8+2*kc+{0,1}
    float dv0 = v0 ? g_dinv[row0] : 0.0f;
    float dv1 = v1 ? g_dinv[row1] : 0.0f;
    int cb = 2 * kc;
#pragma unroll
    for (int nt = 0; nt < 17; nt++) {
        int c = nt * 8 + cb;
        if (v0)
            *(__half2*)(g_A16 + (size_t)row0 * DPH + c) =
                __floats2half2_rn(dv0 * acc[nt][0], dv0 * acc[nt][1]);
        if (v1)
            *(__half2*)(g_A16 + (size_t)row1 * DPH + c) =
                __floats2half2_rn(dv1 * acc[nt][2], dv1 * acc[nt][3]);
    }
    if (kc == 0) {   // zero pads cols 136..143 (8 halves = 16B)
        if (v0) *(uint4*)(g_A16 + (size_t)row0 * DPH + 136) = make_uint4(0, 0, 0, 0);
        if (v1) *(uint4*)(g_A16 + (size_t)row1 * DPH + 136) = make_uint4(0, 0, 0, 0);
    }
}

// ------------------------------------------------------------------
// Warp-per-node CSR gather (fp16 messages, fp32 accum) + fused epilogue.
__global__ __launch_bounds__(256)
void gather_post_kernel(const __half* __restrict__ A, float* __restrict__ Cout,
                        const float* __restrict__ post, int do_pool,
                        const int* __restrict__ batch) {
    int gw = (blockIdx.x * blockDim.x + threadIdx.x) >> 5;
    if (gw >= N_NODES) return;
    int lane = threadIdx.x & 31;
    int n = gw;

    int lo = __ldg(&g_off[n]);
    int hi = __ldg(&g_off[n + 1]);

    float a[8];
#pragma unroll
    for (int i = 0; i < 8; i++) a[i] = 0.0f;

    if (lane < 17) {
        const uint4 v = __ldg((const uint4*)(A + (size_t)n * DPH) + lane);
        const __half2* h = (const __half2*)&v;
#pragma unroll
        for (int q = 0; q < 4; q++) {
            float2 f = __half22float2(h[q]);
            a[2 * q] += f.x; a[2 * q + 1] += f.y;
        }
    }

    int e = lo;
    for (; e + 32 <= hi; e += 32) {
        int src = __ldg(&g_csr[e + lane]);
#pragma unroll 4
        for (int j = 0; j < 32; j++) {
            int sj = __shfl_sync(0xffffffffu, src, j);
            if (lane < 17) {
                const uint4 v = __ldg((const uint4*)(A + (size_t)sj * DPH) + lane);
                const __half2* h = (const __half2*)&v;
#pragma unroll
                for (int q = 0; q < 4; q++) {
                    float2 f = __half22float2(h[q]);
                    a[2 * q] += f.x; a[2 * q + 1] += f.y;
                }
            }
        }
    }
    for (; e < hi; e++) {
        int sj = __ldg(&g_csr[e]);
        if (lane < 17) {
            const uint4 v = __ldg((const uint4*)(A + (size_t)sj * DPH) + lane);
            const __half2* h = (const __half2*)&v;
#pragma unroll
            for (int q = 0; q < 4; q++) {
                float2 f = __half22float2(h[q]);
                a[2 * q] += f.x; a[2 * q + 1] += f.y;
            }
        }
    }

    if (lane >= 17) return;

    float dv = __ldg(&g_dinv[n]);
    const float* bb = post;
    const float* ss = post + DP;
    const float* tt = post + 2 * DP;

    int c0 = 8 * lane;
    float o[8];
#pragma unroll
    for (int i = 0; i < 8; i++) {
        float v = fmaf(dv, a[i], __ldg(&bb[c0 + i]));
        o[i] = fmaf(fmaxf(v, 0.0f), __ldg(&ss[c0 + i]), __ldg(&tt[c0 + i]));
    }

    if (!do_pool) {
        float4* Cn = (float4*)(Cout + (size_t)n * DP + c0);
        Cn[0] = make_float4(o[0], o[1], o[2], o[3]);
        Cn[1] = make_float4(o[4], o[5], o[6], o[7]);
    } else {
        int g = __ldg(&batch[n]);
        float* dst = g_P + (size_t)g * DP + c0;
        unsigned long long p0 = (unsigned long long)__cvta_generic_to_global(dst);
        asm volatile("red.global.add.v4.f32 [%0], {%1,%2,%3,%4};"
                     :: "l"(p0), "f"(o[0]), "f"(o[1]), "f"(o[2]), "f"(o[3]) : "memory");
        unsigned long long p1 = (unsigned long long)__cvta_generic_to_global(dst + 4);
        asm volatile("red.global.add.v4.f32 [%0], {%1,%2,%3,%4};"
                     :: "l"(p1), "f"(o[4]), "f"(o[5]), "f"(o[6]), "f"(o[7]) : "memory");
    }
}

// ------------------------------------------------------------------
__device__ __forceinline__ int lbound(const int* b, int n, int v) {
    int lo = 0, hi = n;
    while (lo < hi) { int m = (lo + hi) >> 1; if (b[m] < v) lo = m + 1; else hi = m; }
    return lo;
}

__global__ void cntg_kernel(const int* __restrict__ batch) {
    int g = blockIdx.x * blockDim.x + threadIdx.x;
    if (g < N_GRAPHS)
        g_cntg[g] = lbound(batch, N_NODES, g + 1) - lbound(batch, N_NODES, g);
}

__global__ void divide_kernel(float* __restrict__ out) {
    int idx = blockIdx.x * blockDim.x + threadIdx.x;
    if (idx >= N_GRAPHS * D) return;
    int g = idx / D;
    int c = idx - g * D;
    float cnt = (float)g_cntg[g];
    out[idx] = g_P[(size_t)g * DP + c] / fmaxf(cnt, 1.0f);
}

// ------------------------------------------------------------------
extern "C" void kernel_launch(void* const* d_in, const int* in_sizes, int n_in,
                              void* d_out, int out_size) {
    const float* x     = (const float*)d_in[0];
    const int*   ei    = (const int*)d_in[1];
    const int*   batch = (const int*)d_in[2];
    const float* W1  = (const float*)d_in[3];
    const float* b1  = (const float*)d_in[4];
    const float* W2  = (const float*)d_in[5];
    const float* b2  = (const float*)d_in[6];
    const float* g1  = (const float*)d_in[7];
    const float* be1 = (const float*)d_in[8];
    const float* rm1 = (const float*)d_in[9];
    const float* rv1 = (const float*)d_in[10];
    const float* g2  = (const float*)d_in[11];
    const float* be2 = (const float*)d_in[12];
    const float* rm2 = (const float*)d_in[13];
    const float* rv2 = (const float*)d_in[14];
    float* out = (float*)d_out;

    __half* pA;
    float *pC, *pP1, *pP2;
    cudaGetSymbolAddress((void**)&pA, g_A16);
    cudaGetSymbolAddress((void**)&pC, g_C);
    cudaGetSymbolAddress((void**)&pP1, g_post1);
    cudaGetSymbolAddress((void**)&pP2, g_post2);

    const int smem = 136 * 136 * (int)sizeof(uint32_t);          // 74 KB -> 3 blocks/SM
    cudaFuncSetAttribute((const void*)gemm_tc_kernel,
                         cudaFuncAttributeMaxDynamicSharedMemorySize, smem);

    const int TB = 256;
    const int gemm_blocks   = (N_NODES + 128 - 1) / 128;          // 391
    const int gather_blocks = (N_NODES * 32 + TB - 1) / TB;       // warp per node

    // launch order puts gemm_tc at position #4 so ncu captures it
    zero_fused_kernel<<<(N_GRAPHS * DP + TB - 1) / TB, TB>>>();
    count_deg_kernel<<<(N_EDGES + TB - 1) / TB, TB>>>(ei);
    dinv_kernel<<<(N_NODES + TB - 1) / TB, TB>>>();

    // ---- layer 1 GEMM (#4) ----
    gemm_tc_kernel<<<gemm_blocks, TB, smem>>>(x, D, W1);

    // ---- CSR build (independent of gemm) ----
    scan1_kernel<<<SCAN_NB, SCAN_B>>>();
    scan2_kernel<<<1, 32>>>();
    scan3_kernel<<<SCAN_NB, SCAN_B>>>();
    fill_csr_kernel<<<(N_EDGES + TB - 1) / TB, TB>>>(ei);
    prep_post_kernel<<<1, DP>>>(b1, g1, be1, rm1, rv1, pP1);
    prep_post_kernel<<<1, DP>>>(b2, g2, be2, rm2, rv2, pP2);

    // ---- layer 1 gather ----
    gather_post_kernel<<<gather_blocks, TB>>>(pA, pC, pP1, 0, batch);

    // ---- layer 2 (+ fused pool accumulate) ----
    gemm_tc_kernel<<<gemm_blocks, TB, smem>>>(pC, DP, W2);
    gather_post_kernel<<<gather_blocks, TB>>>(pA, pC, pP2, 1, batch);

    // ---- per-graph mean ----
    cntg_kernel<<<(N_GRAPHS + TB - 1) / TB, TB>>>(batch);
    divide_kernel<<<(N_GRAPHS * D + TB - 1) / TB, TB>>>(out);
}

// round 8
// speedup vs baseline: 1.0692x; 1.0692x over previous
#include <cuda_runtime.h>
#include <cuda_fp16.h>
#include <cstdint>

#define N_NODES 50000
#define N_EDGES 1600000
#define N_GRAPHS 2048
#define D 133
#define DP 136           // fp32 padded row (floats)
#define DPH 144          // fp16 padded row (halves) = 288B
#define EPSV 1e-5f
#define SCAN_B 1024
#define SCAN_NB ((N_NODES + SCAN_B - 1) / SCAN_B)   // 49

// -------- scratch (static device globals; no runtime allocation) --------
__device__ __align__(16) __half g_A16[(size_t)N_NODES * DPH];  // gemm out, dinv-scaled, fp16
__device__ __align__(16) float  g_C[(size_t)N_NODES * DP];     // gather out / layer-2 input
__device__ __align__(16) float  g_P[(size_t)N_GRAPHS * DP];    // pool accumulator
__device__ __align__(16) uint32_t g_W1t[136 * 136];            // W1 tf32, padded
__device__ __align__(16) uint32_t g_W2t[136 * 136];            // W2 tf32, padded
__device__ float g_dinv[N_NODES];
__device__ int   g_cnt[N_NODES];
__device__ int   g_off[N_NODES + 1];
__device__ int   g_cursor[N_NODES];
__device__ int   g_csr[N_EDGES];
__device__ int   g_bsum[SCAN_NB];
__device__ int   g_cntg[N_GRAPHS];
__device__ float g_post1[3 * DP];    // bias | s | t   (zero-padded)
__device__ float g_post2[3 * DP];

// ------------------------------------------------------------------
__global__ void zero_fused_kernel() {
    int i = blockIdx.x * blockDim.x + threadIdx.x;
    if (i < N_GRAPHS * DP) g_P[i] = 0.0f;
    if (i < N_NODES)       g_cnt[i] = 0;
}

__global__ void count_deg_kernel(const int* __restrict__ ei) {
    int e = blockIdx.x * blockDim.x + threadIdx.x;
    if (e < N_EDGES) atomicAdd(&g_cnt[__ldg(&ei[N_EDGES + e])], 1);
}

__global__ void dinv_kernel() {
    int i = blockIdx.x * blockDim.x + threadIdx.x;
    if (i < N_NODES) g_dinv[i] = rsqrtf((float)(g_cnt[i] + 1));   // +1 self-loop
}

// ---- 3-kernel exclusive scan of g_cnt -> g_off ----
__global__ void scan1_kernel() {
    __shared__ int sh[SCAN_B];
    int t = threadIdx.x;
    int i = blockIdx.x * SCAN_B + t;
    int v = (i < N_NODES) ? g_cnt[i] : 0;
    sh[t] = v;
    __syncthreads();
#pragma unroll
    for (int d = 1; d < SCAN_B; d <<= 1) {
        int x = (t >= d) ? sh[t - d] : 0;
        __syncthreads();
        sh[t] += x;
        __syncthreads();
    }
    if (i < N_NODES) g_off[i] = sh[t] - v;           // exclusive, local
    if (t == SCAN_B - 1) g_bsum[blockIdx.x] = sh[t];
}

__global__ void scan2_kernel() {
    if (threadIdx.x == 0) {
        int acc = 0;
        for (int b = 0; b < SCAN_NB; b++) {
            int v = g_bsum[b];
            g_bsum[b] = acc;
            acc += v;
        }
    }
}

__global__ void scan3_kernel() {
    int i = blockIdx.x * blockDim.x + threadIdx.x;
    if (i < N_NODES) {
        int o = g_off[i] + g_bsum[i / SCAN_B];
        g_off[i] = o;
        g_cursor[i] = o;
    }
    if (i == 0) g_off[N_NODES] = N_EDGES;
}

__global__ void fill_csr_kernel(const int* __restrict__ ei) {
    int e = blockIdx.x * blockDim.x + threadIdx.x;
    if (e < N_EDGES) {
        int r = __ldg(&ei[e]);
        int c = __ldg(&ei[N_EDGES + e]);
        int pos = atomicAdd(&g_cursor[c], 1);
        g_csr[pos] = r;
    }
}

// ---- per-layer fused BN constants: bias | s | t, zero-padded to DP ----
__global__ void prep_post_kernel(const float* __restrict__ bias, const float* __restrict__ gam,
                                 const float* __restrict__ beta, const float* __restrict__ rm,
                                 const float* __restrict__ rv, float* __restrict__ dst) {
    int c = threadIdx.x;
    if (c >= DP) return;
    float bb = 0.0f, ss = 0.0f, tt = 0.0f;
    if (c < D) {
        bb = bias[c];
        float sc = gam[c] * rsqrtf(rv[c] + EPSV);
        ss = sc;
        tt = beta[c] - rm[c] * sc;
    }
    dst[c] = bb; dst[DP + c] = ss; dst[2 * DP + c] = tt;
}

// ------------------------------------------------------------------
__device__ __forceinline__ uint32_t f2tf32(float f) {
    uint32_t r;
    asm("cvt.rna.tf32.f32 %0, %1;" : "=r"(r) : "f"(f));
    return r;
}

__global__ void w_cvt_kernel(const float* __restrict__ W, uint32_t* __restrict__ Wt) {
    int i = blockIdx.x * blockDim.x + threadIdx.x;
    if (i >= 136 * 136) return;
    int k = i / 136, n = i - k * 136;
    Wt[i] = (k < D && n < D) ? f2tf32(__ldg(&W[k * D + n])) : 0u;
}

__device__ __forceinline__ void mma_tf32(float* d,
                                         uint32_t a0, uint32_t a1, uint32_t a2, uint32_t a3,
                                         uint32_t b0, uint32_t b1) {
    asm volatile("mma.sync.aligned.m16n8k8.row.col.f32.tf32.tf32.f32 "
                 "{%0,%1,%2,%3}, {%4,%5,%6,%7}, {%8,%9}, {%0,%1,%2,%3};"
                 : "+f"(d[0]), "+f"(d[1]), "+f"(d[2]), "+f"(d[3])
                 : "r"(a0), "r"(a1), "r"(a2), "r"(a3), "r"(b0), "r"(b1));
}

// Tensor-core GEMM: g_A16[row] = fp16( dinv[row] * (X @ W) ), pads zeroed.
// n-split: warp pair shares 16 rows; colhalf 0 -> n-tiles 0..8, colhalf 1 -> 9..16.
// acc = 36 regs -> ~64 total -> smem-limited 3 blocks/SM (24 warps).
// Block: 8 warps = 4 row-groups x 2 col-halves = 64 rows.
__global__ __launch_bounds__(256)
void gemm_tc_kernel(const float* __restrict__ X, int ldx,
                    const uint32_t* __restrict__ Wt) {
    extern __shared__ uint32_t ws[];         // [136][136] tf32 bits

    int tid  = threadIdx.x;
    int w    = tid >> 5;
    int lane = tid & 31;

    // vectorized W copy (pre-converted tf32): 4624 uint4
    {
        const uint4* src = (const uint4*)Wt;
        uint4* dst = (uint4*)ws;
#pragma unroll 5
        for (int i = tid; i < (136 * 136) / 4; i += 256) dst[i] = __ldg(&src[i]);
    }
    __syncthreads();

    const int r0 = lane >> 2;        // A row group / B n
    const int kc = lane & 3;         // A k within quad / B k
    const int colhalf = w & 1;
    const int ntBase = colhalf * 9;
    const int ntCnt  = 9 - colhalf;  // 9 or 8 tiles

    int rowbase = blockIdx.x * 64 + (w >> 1) * 16;
    int row0 = rowbase + r0;
    int row1 = row0 + 8;
    bool v0 = row0 < N_NODES;
    bool v1 = row1 < N_NODES;
    const float* X0 = X + (size_t)row0 * ldx;
    const float* X1 = X + (size_t)row1 * ldx;

    float acc[9][4];
#pragma unroll
    for (int j = 0; j < 9; j++)
#pragma unroll
        for (int q = 0; q < 4; q++) acc[j][q] = 0.0f;

    // ks 0..15: cols <= 127 < 133, no column predication needed
#pragma unroll 4
    for (int ks = 0; ks < 16; ks++) {
        int c0 = ks * 8 + kc;
        uint32_t a0 = v0 ? f2tf32(__ldg(X0 + c0)) : 0u;
        uint32_t a1 = v1 ? f2tf32(__ldg(X1 + c0)) : 0u;
        uint32_t a2 = v0 ? f2tf32(__ldg(X0 + c0 + 4)) : 0u;
        uint32_t a3 = v1 ? f2tf32(__ldg(X1 + c0 + 4)) : 0u;
        const uint32_t* wr0 = ws + (ks * 8 + kc) * 136 + r0 + ntBase * 8;
        const uint32_t* wr1 = wr0 + 4 * 136;
#pragma unroll
        for (int j = 0; j < 9; j++) {
            if (j < ntCnt)
                mma_tf32(acc[j], a0, a1, a2, a3, wr0[j * 8], wr1[j * 8]);
        }
    }
    {   // tail ks=16: c0 = 128+kc (<133 always); c1 = 132+kc valid only for kc==0
        int c0 = 128 + kc;
        bool pv = (kc == 0);
        uint32_t a0 = v0 ? f2tf32(__ldg(X0 + c0)) : 0u;
        uint32_t a1 = v1 ? f2tf32(__ldg(X1 + c0)) : 0u;
        uint32_t a2 = (v0 && pv) ? f2tf32(__ldg(X0 + 132)) : 0u;
        uint32_t a3 = (v1 && pv) ? f2tf32(__ldg(X1 + 132)) : 0u;
        const uint32_t* wr0 = ws + (128 + kc) * 136 + r0 + ntBase * 8;
        const uint32_t* wr1 = wr0 + 4 * 136;
#pragma unroll
        for (int j = 0; j < 9; j++) {
            if (j < ntCnt)
                mma_tf32(acc[j], a0, a1, a2, a3, wr0[j * 8], wr1[j * 8]);
        }
    }

    // epilogue: dinv scale -> fp16 half2 stores
    float dv0 = v0 ? g_dinv[row0] : 0.0f;
    float dv1 = v1 ? g_dinv[row1] : 0.0f;
    int cb = 2 * kc;
#pragma unroll
    for (int j = 0; j < 9; j++) {
        if (j < ntCnt) {
            int c = (ntBase + j) * 8 + cb;
            if (v0)
                *(__half2*)(g_A16 + (size_t)row0 * DPH + c) =
                    __floats2half2_rn(dv0 * acc[j][0], dv0 * acc[j][1]);
            if (v1)
                *(__half2*)(g_A16 + (size_t)row1 * DPH + c) =
                    __floats2half2_rn(dv1 * acc[j][2], dv1 * acc[j][3]);
        }
    }
    if (colhalf == 1 && kc == 0) {   // zero pads cols 136..143 (16B)
        if (v0) *(uint4*)(g_A16 + (size_t)row0 * DPH + 136) = make_uint4(0, 0, 0, 0);
        if (v1) *(uint4*)(g_A16 + (size_t)row1 * DPH + 136) = make_uint4(0, 0, 0, 0);
    }
}

// ------------------------------------------------------------------
// Warp-per-node CSR gather (fp16 messages, fp32 accum) + fused epilogue.
__global__ __launch_bounds__(256)
void gather_post_kernel(const __half* __restrict__ A, float* __restrict__ Cout,
                        const float* __restrict__ post, int do_pool,
                        const int* __restrict__ batch) {
    int gw = (blockIdx.x * blockDim.x + threadIdx.x) >> 5;
    if (gw >= N_NODES) return;
    int lane = threadIdx.x & 31;
    int n = gw;

    int lo = __ldg(&g_off[n]);
    int hi = __ldg(&g_off[n + 1]);

    float a[8];
#pragma unroll
    for (int i = 0; i < 8; i++) a[i] = 0.0f;

    if (lane < 17) {
        const uint4 v = __ldg((const uint4*)(A + (size_t)n * DPH) + lane);
        const __half2* h = (const __half2*)&v;
#pragma unroll
        for (int q = 0; q < 4; q++) {
            float2 f = __half22float2(h[q]);
            a[2 * q] += f.x; a[2 * q + 1] += f.y;
        }
    }

    int e = lo;
    for (; e + 32 <= hi; e += 32) {
        int src = __ldg(&g_csr[e + lane]);
#pragma unroll 4
        for (int j = 0; j < 32; j++) {
            int sj = __shfl_sync(0xffffffffu, src, j);
            if (lane < 17) {
                const uint4 v = __ldg((const uint4*)(A + (size_t)sj * DPH) + lane);
                const __half2* h = (const __half2*)&v;
#pragma unroll
                for (int q = 0; q < 4; q++) {
                    float2 f = __half22float2(h[q]);
                    a[2 * q] += f.x; a[2 * q + 1] += f.y;
                }
            }
        }
    }
    for (; e < hi; e++) {
        int sj = __ldg(&g_csr[e]);
        if (lane < 17) {
            const uint4 v = __ldg((const uint4*)(A + (size_t)sj * DPH) + lane);
            const __half2* h = (const __half2*)&v;
#pragma unroll
            for (int q = 0; q < 4; q++) {
                float2 f = __half22float2(h[q]);
                a[2 * q] += f.x; a[2 * q + 1] += f.y;
            }
        }
    }

    if (lane >= 17) return;

    float dv = __ldg(&g_dinv[n]);
    const float* bb = post;
    const float* ss = post + DP;
    const float* tt = post + 2 * DP;

    int c0 = 8 * lane;
    float o[8];
#pragma unroll
    for (int i = 0; i < 8; i++) {
        float v = fmaf(dv, a[i], __ldg(&bb[c0 + i]));
        o[i] = fmaf(fmaxf(v, 0.0f), __ldg(&ss[c0 + i]), __ldg(&tt[c0 + i]));
    }

    if (!do_pool) {
        float4* Cn = (float4*)(Cout + (size_t)n * DP + c0);
        Cn[0] = make_float4(o[0], o[1], o[2], o[3]);
        Cn[1] = make_float4(o[4], o[5], o[6], o[7]);
    } else {
        int g = __ldg(&batch[n]);
        float* dst = g_P + (size_t)g * DP + c0;
        unsigned long long p0 = (unsigned long long)__cvta_generic_to_global(dst);
        asm volatile("red.global.add.v4.f32 [%0], {%1,%2,%3,%4};"
                     :: "l"(p0), "f"(o[0]), "f"(o[1]), "f"(o[2]), "f"(o[3]) : "memory");
        unsigned long long p1 = (unsigned long long)__cvta_generic_to_global(dst + 4);
        asm volatile("red.global.add.v4.f32 [%0], {%1,%2,%3,%4};"
                     :: "l"(p1), "f"(o[4]), "f"(o[5]), "f"(o[6]), "f"(o[7]) : "memory");
    }
}

// ------------------------------------------------------------------
__device__ __forceinline__ int lbound(const int* b, int n, int v) {
    int lo = 0, hi = n;
    while (lo < hi) { int m = (lo + hi) >> 1; if (b[m] < v) lo = m + 1; else hi = m; }
    return lo;
}

__global__ void cntg_kernel(const int* __restrict__ batch) {
    int g = blockIdx.x * blockDim.x + threadIdx.x;
    if (g < N_GRAPHS)
        g_cntg[g] = lbound(batch, N_NODES, g + 1) - lbound(batch, N_NODES, g);
}

__global__ void divide_kernel(float* __restrict__ out) {
    int idx = blockIdx.x * blockDim.x + threadIdx.x;
    if (idx >= N_GRAPHS * D) return;
    int g = idx / D;
    int c = idx - g * D;
    float cnt = (float)g_cntg[g];
    out[idx] = g_P[(size_t)g * DP + c] / fmaxf(cnt, 1.0f);
}

// ------------------------------------------------------------------
extern "C" void kernel_launch(void* const* d_in, const int* in_sizes, int n_in,
                              void* d_out, int out_size) {
    const float* x     = (const float*)d_in[0];
    const int*   ei    = (const int*)d_in[1];
    const int*   batch = (const int*)d_in[2];
    const float* W1  = (const float*)d_in[3];
    const float* b1  = (const float*)d_in[4];
    const float* W2  = (const float*)d_in[5];
    const float* b2  = (const float*)d_in[6];
    const float* g1  = (const float*)d_in[7];
    const float* be1 = (const float*)d_in[8];
    const float* rm1 = (const float*)d_in[9];
    const float* rv1 = (const float*)d_in[10];
    const float* g2  = (const float*)d_in[11];
    const float* be2 = (const float*)d_in[12];
    const float* rm2 = (const float*)d_in[13];
    const float* rv2 = (const float*)d_in[14];
    float* out = (float*)d_out;

    __half* pA;
    float *pC, *pP1, *pP2;
    uint32_t *pW1t, *pW2t;
    cudaGetSymbolAddress((void**)&pA, g_A16);
    cudaGetSymbolAddress((void**)&pC, g_C);
    cudaGetSymbolAddress((void**)&pP1, g_post1);
    cudaGetSymbolAddress((void**)&pP2, g_post2);
    cudaGetSymbolAddress((void**)&pW1t, g_W1t);
    cudaGetSymbolAddress((void**)&pW2t, g_W2t);

    // side stream + fork/join events, created once (no device allocation)
    static cudaStream_t s_side = nullptr;
    static cudaEvent_t ev_fork = nullptr, ev_join = nullptr;
    if (!s_side) {
        cudaStreamCreateWithFlags(&s_side, cudaStreamNonBlocking);
        cudaEventCreateWithFlags(&ev_fork, cudaEventDisableTiming);
        cudaEventCreateWithFlags(&ev_join, cudaEventDisableTiming);
    }

    const int smem = 136 * 136 * (int)sizeof(uint32_t);          // 74 KB -> 3 blocks/SM
    cudaFuncSetAttribute((const void*)gemm_tc_kernel,
                         cudaFuncAttributeMaxDynamicSharedMemorySize, smem);

    const int TB = 256;
    const int gemm_blocks   = (N_NODES + 63) / 64;                // 782
    const int gather_blocks = (N_NODES * 32 + TB - 1) / TB;       // warp per node

    // ---- main stream: prep for gemm1 ----
    w_cvt_kernel<<<(136 * 136 + TB - 1) / TB, TB>>>(W1, pW1t);
    zero_fused_kernel<<<(N_GRAPHS * DP + TB - 1) / TB, TB>>>();
    count_deg_kernel<<<(N_EDGES + TB - 1) / TB, TB>>>(ei);

    // ---- fork: CSR build + misc on side stream, overlapped with gemm1 ----
    cudaEventRecord(ev_fork, 0);
    cudaStreamWaitEvent(s_side, ev_fork, 0);
    scan1_kernel<<<SCAN_NB, SCAN_B, 0, s_side>>>();
    scan2_kernel<<<1, 32, 0, s_side>>>();
    scan3_kernel<<<SCAN_NB, SCAN_B, 0, s_side>>>();
    fill_csr_kernel<<<(N_EDGES + TB - 1) / TB, TB, 0, s_side>>>(ei);
    w_cvt_kernel<<<(136 * 136 + TB - 1) / TB, TB, 0, s_side>>>(W2, pW2t);
    prep_post_kernel<<<1, DP, 0, s_side>>>(b1, g1, be1, rm1, rv1, pP1);
    prep_post_kernel<<<1, DP, 0, s_side>>>(b2, g2, be2, rm2, rv2, pP2);
    cntg_kernel<<<(N_GRAPHS + TB - 1) / TB, TB, 0, s_side>>>(batch);
    cudaEventRecord(ev_join, s_side);

    // ---- main stream: dinv + gemm1 (concurrent with side) ----
    dinv_kernel<<<(N_NODES + TB - 1) / TB, TB>>>();
    gemm_tc_kernel<<<gemm_blocks, TB, smem>>>(x, D, pW1t);

    // ---- join, then the serial tail ----
    cudaStreamWaitEvent(0, ev_join, 0);
    gather_post_kernel<<<gather_blocks, TB>>>(pA, pC, pP1, 0, batch);
    gemm_tc_kernel<<<gemm_blocks, TB, smem>>>(pC, DP, pW2t);
    gather_post_kernel<<<gather_blocks, TB>>>(pA, pC, pP2, 1, batch);
    divide_kernel<<<(N_GRAPHS * D + TB - 1) / TB, TB>>>(out);
}

// round 9
// speedup vs baseline: 1.0748x; 1.0053x over previous
#include <cuda_runtime.h>
#include <cuda_fp16.h>
#include <cstdint>

#define N_NODES 50000
#define N_EDGES 1600000
#define N_GRAPHS 2048
#define D 133
#define DP 136           // fp32 padded row (floats)
#define DPH 144          // fp16 padded row (halves) = 288B
#define EPSV 1e-5f
#define SCAN_B 1024
#define SCAN_NB ((N_NODES + SCAN_B - 1) / SCAN_B)   // 49

// -------- scratch (static device globals; no runtime allocation) --------
__device__ __align__(16) __half g_A16[(size_t)N_NODES * DPH];  // gemm out, dinv-scaled, fp16
__device__ __align__(16) float  g_C[(size_t)N_NODES * DP];     // gather out / layer-2 input
__device__ __align__(16) float  g_P[(size_t)N_GRAPHS * DP];    // pool accumulator
__device__ __align__(16) uint32_t g_W1t[136 * 136];            // W1 tf32, padded
__device__ __align__(16) uint32_t g_W2t[136 * 136];            // W2 tf32, padded
__device__ float g_dinv[N_NODES];
__device__ int   g_cnt[N_NODES];
__device__ int   g_off[N_NODES + 1];
__device__ int   g_cursor[N_NODES];
__device__ int   g_csr[N_EDGES];
__device__ int   g_bsum[SCAN_NB];
__device__ int   g_cntg[N_GRAPHS];
__device__ float g_post1[3 * DP];    // bias | s | t   (zero-padded)
__device__ float g_post2[3 * DP];

// ------------------------------------------------------------------
__global__ void zero_fused_kernel() {
    int i = blockIdx.x * blockDim.x + threadIdx.x;
    if (i < N_GRAPHS * DP) g_P[i] = 0.0f;
    if (i < N_NODES)       g_cnt[i] = 0;
}

__global__ void count_deg_kernel(const int* __restrict__ ei) {
    int e = blockIdx.x * blockDim.x + threadIdx.x;
    if (e < N_EDGES) atomicAdd(&g_cnt[__ldg(&ei[N_EDGES + e])], 1);
}

__global__ void dinv_kernel() {
    int i = blockIdx.x * blockDim.x + threadIdx.x;
    if (i < N_NODES) g_dinv[i] = rsqrtf((float)(g_cnt[i] + 1));   // +1 self-loop
}

// ---- 3-kernel exclusive scan of g_cnt -> g_off ----
__global__ void scan1_kernel() {
    __shared__ int sh[SCAN_B];
    int t = threadIdx.x;
    int i = blockIdx.x * SCAN_B + t;
    int v = (i < N_NODES) ? g_cnt[i] : 0;
    sh[t] = v;
    __syncthreads();
#pragma unroll
    for (int d = 1; d < SCAN_B; d <<= 1) {
        int x = (t >= d) ? sh[t - d] : 0;
        __syncthreads();
        sh[t] += x;
        __syncthreads();
    }
    if (i < N_NODES) g_off[i] = sh[t] - v;           // exclusive, local
    if (t == SCAN_B - 1) g_bsum[blockIdx.x] = sh[t];
}

__global__ void scan2_kernel() {
    if (threadIdx.x == 0) {
        int acc = 0;
        for (int b = 0; b < SCAN_NB; b++) {
            int v = g_bsum[b];
            g_bsum[b] = acc;
            acc += v;
        }
    }
}

__global__ void scan3_kernel() {
    int i = blockIdx.x * blockDim.x + threadIdx.x;
    if (i < N_NODES) {
        int o = g_off[i] + g_bsum[i / SCAN_B];
        g_off[i] = o;
        g_cursor[i] = o;
    }
    if (i == 0) g_off[N_NODES] = N_EDGES;
}

__global__ void fill_csr_kernel(const int* __restrict__ ei) {
    int e = blockIdx.x * blockDim.x + threadIdx.x;
    if (e < N_EDGES) {
        int r = __ldg(&ei[e]);
        int c = __ldg(&ei[N_EDGES + e]);
        int pos = atomicAdd(&g_cursor[c], 1);
        g_csr[pos] = r;
    }
}

// ---- per-layer fused BN constants: bias | s | t, zero-padded to DP ----
__global__ void prep_post_kernel(const float* __restrict__ bias, const float* __restrict__ gam,
                                 const float* __restrict__ beta, const float* __restrict__ rm,
                                 const float* __restrict__ rv, float* __restrict__ dst) {
    int c = threadIdx.x;
    if (c >= DP) return;
    float bb = 0.0f, ss = 0.0f, tt = 0.0f;
    if (c < D) {
        bb = bias[c];
        float sc = gam[c] * rsqrtf(rv[c] + EPSV);
        ss = sc;
        tt = beta[c] - rm[c] * sc;
    }
    dst[c] = bb; dst[DP + c] = ss; dst[2 * DP + c] = tt;
}

// ------------------------------------------------------------------
__device__ __forceinline__ uint32_t f2tf32(float f) {
    uint32_t r;
    asm("cvt.rna.tf32.f32 %0, %1;" : "=r"(r) : "f"(f));
    return r;
}

__global__ void w_cvt_kernel(const float* __restrict__ W, uint32_t* __restrict__ Wt) {
    int i = blockIdx.x * blockDim.x + threadIdx.x;
    if (i >= 136 * 136) return;
    int k = i / 136, n = i - k * 136;
    Wt[i] = (k < D && n < D) ? f2tf32(__ldg(&W[k * D + n])) : 0u;
}

__device__ __forceinline__ void mma_tf32(float* d,
                                         uint32_t a0, uint32_t a1, uint32_t a2, uint32_t a3,
                                         uint32_t b0, uint32_t b1) {
    asm volatile("mma.sync.aligned.m16n8k8.row.col.f32.tf32.tf32.f32 "
                 "{%0,%1,%2,%3}, {%4,%5,%6,%7}, {%8,%9}, {%0,%1,%2,%3};"
                 : "+f"(d[0]), "+f"(d[1]), "+f"(d[2]), "+f"(d[3])
                 : "r"(a0), "r"(a1), "r"(a2), "r"(a3), "r"(b0), "r"(b1));
}

// Tensor-core GEMM: g_A16[row] = fp16( dinv[row] * (X @ W) ), pads zeroed.
// n-split: warp pair shares 16 rows; colhalf 0 -> n-tiles 0..8, colhalf 1 -> 9..16.
// acc = 36 regs -> ~64 total -> smem-limited 3 blocks/SM (24 warps).
// Block: 8 warps = 4 row-groups x 2 col-halves = 64 rows.
__global__ __launch_bounds__(256)
void gemm_tc_kernel(const float* __restrict__ X, int ldx,
                    const uint32_t* __restrict__ Wt) {
    extern __shared__ uint32_t ws[];         // [136][136] tf32 bits

    int tid  = threadIdx.x;
    int w    = tid >> 5;
    int lane = tid & 31;

    // vectorized W copy (pre-converted tf32): 4624 uint4
    {
        const uint4* src = (const uint4*)Wt;
        uint4* dst = (uint4*)ws;
#pragma unroll 5
        for (int i = tid; i < (136 * 136) / 4; i += 256) dst[i] = __ldg(&src[i]);
    }
    __syncthreads();

    const int r0 = lane >> 2;        // A row group / B n
    const int kc = lane & 3;         // A k within quad / B k
    const int colhalf = w & 1;
    const int ntBase = colhalf * 9;
    const int ntCnt  = 9 - colhalf;  // 9 or 8 tiles

    int rowbase = blockIdx.x * 64 + (w >> 1) * 16;
    int row0 = rowbase + r0;
    int row1 = row0 + 8;
    bool v0 = row0 < N_NODES;
    bool v1 = row1 < N_NODES;
    const float* X0 = X + (size_t)row0 * ldx;
    const float* X1 = X + (size_t)row1 * ldx;

    float acc[9][4];
#pragma unroll
    for (int j = 0; j < 9; j++)
#pragma unroll
        for (int q = 0; q < 4; q++) acc[j][q] = 0.0f;

    // ks 0..15: cols <= 127 < 133, no column predication needed
#pragma unroll 4
    for (int ks = 0; ks < 16; ks++) {
        int c0 = ks * 8 + kc;
        uint32_t a0 = v0 ? f2tf32(__ldg(X0 + c0)) : 0u;
        uint32_t a1 = v1 ? f2tf32(__ldg(X1 + c0)) : 0u;
        uint32_t a2 = v0 ? f2tf32(__ldg(X0 + c0 + 4)) : 0u;
        uint32_t a3 = v1 ? f2tf32(__ldg(X1 + c0 + 4)) : 0u;
        const uint32_t* wr0 = ws + (ks * 8 + kc) * 136 + r0 + ntBase * 8;
        const uint32_t* wr1 = wr0 + 4 * 136;
#pragma unroll
        for (int j = 0; j < 9; j++) {
            if (j < ntCnt)
                mma_tf32(acc[j], a0, a1, a2, a3, wr0[j * 8], wr1[j * 8]);
        }
    }
    {   // tail ks=16: c0 = 128+kc (<133 always); c1 = 132+kc valid only for kc==0
        int c0 = 128 + kc;
        bool pv = (kc == 0);
        uint32_t a0 = v0 ? f2tf32(__ldg(X0 + c0)) : 0u;
        uint32_t a1 = v1 ? f2tf32(__ldg(X1 + c0)) : 0u;
        uint32_t a2 = (v0 && pv) ? f2tf32(__ldg(X0 + 132)) : 0u;
        uint32_t a3 = (v1 && pv) ? f2tf32(__ldg(X1 + 132)) : 0u;
        const uint32_t* wr0 = ws + (128 + kc) * 136 + r0 + ntBase * 8;
        const uint32_t* wr1 = wr0 + 4 * 136;
#pragma unroll
        for (int j = 0; j < 9; j++) {
            if (j < ntCnt)
                mma_tf32(acc[j], a0, a1, a2, a3, wr0[j * 8], wr1[j * 8]);
        }
    }

    // epilogue: dinv scale -> fp16 half2 stores
    float dv0 = v0 ? g_dinv[row0] : 0.0f;
    float dv1 = v1 ? g_dinv[row1] : 0.0f;
    int cb = 2 * kc;
#pragma unroll
    for (int j = 0; j < 9; j++) {
        if (j < ntCnt) {
            int c = (ntBase + j) * 8 + cb;
            if (v0)
                *(__half2*)(g_A16 + (size_t)row0 * DPH + c) =
                    __floats2half2_rn(dv0 * acc[j][0], dv0 * acc[j][1]);
            if (v1)
                *(__half2*)(g_A16 + (size_t)row1 * DPH + c) =
                    __floats2half2_rn(dv1 * acc[j][2], dv1 * acc[j][3]);
        }
    }
    if (colhalf == 1 && kc == 0) {   // zero pads cols 136..143 (16B)
        if (v0) *(uint4*)(g_A16 + (size_t)row0 * DPH + 136) = make_uint4(0, 0, 0, 0);
        if (v1) *(uint4*)(g_A16 + (size_t)row1 * DPH + 136) = make_uint4(0, 0, 0, 0);
    }
}

// ------------------------------------------------------------------
// Warp-per-node CSR gather (fp16 messages, fp32 accum) + fused epilogue.
__global__ __launch_bounds__(256)
void gather_post_kernel(const __half* __restrict__ A, float* __restrict__ Cout,
                        const float* __restrict__ post, int do_pool,
                        const int* __restrict__ batch) {
    int gw = (blockIdx.x * blockDim.x + threadIdx.x) >> 5;
    if (gw >= N_NODES) return;
    int lane = threadIdx.x & 31;
    int n = gw;

    int lo = __ldg(&g_off[n]);
    int hi = __ldg(&g_off[n + 1]);

    float a[8];
#pragma unroll
    for (int i = 0; i < 8; i++) a[i] = 0.0f;

    if (lane < 17) {
        const uint4 v = __ldg((const uint4*)(A + (size_t)n * DPH) + lane);
        const __half2* h = (const __half2*)&v;
#pragma unroll
        for (int q = 0; q < 4; q++) {
            float2 f = __half22float2(h[q]);
            a[2 * q] += f.x; a[2 * q + 1] += f.y;
        }
    }

    int e = lo;
    for (; e + 32 <= hi; e += 32) {
        int src = __ldg(&g_csr[e + lane]);
#pragma unroll 4
        for (int j = 0; j < 32; j++) {
            int sj = __shfl_sync(0xffffffffu, src, j);
            if (lane < 17) {
                const uint4 v = __ldg((const uint4*)(A + (size_t)sj * DPH) + lane);
                const __half2* h = (const __half2*)&v;
#pragma unroll
                for (int q = 0; q < 4; q++) {
                    float2 f = __half22float2(h[q]);
                    a[2 * q] += f.x; a[2 * q + 1] += f.y;
                }
            }
        }
    }
    for (; e < hi; e++) {
        int sj = __ldg(&g_csr[e]);
        if (lane < 17) {
            const uint4 v = __ldg((const uint4*)(A + (size_t)sj * DPH) + lane);
            const __half2* h = (const __half2*)&v;
#pragma unroll
            for (int q = 0; q < 4; q++) {
                float2 f = __half22float2(h[q]);
                a[2 * q] += f.x; a[2 * q + 1] += f.y;
            }
        }
    }

    if (lane >= 17) return;

    float dv = __ldg(&g_dinv[n]);
    const float* bb = post;
    const float* ss = post + DP;
    const float* tt = post + 2 * DP;

    int c0 = 8 * lane;
    float o[8];
#pragma unroll
    for (int i = 0; i < 8; i++) {
        float v = fmaf(dv, a[i], __ldg(&bb[c0 + i]));
        o[i] = fmaf(fmaxf(v, 0.0f), __ldg(&ss[c0 + i]), __ldg(&tt[c0 + i]));
    }

    if (!do_pool) {
        float4* Cn = (float4*)(Cout + (size_t)n * DP + c0);
        Cn[0] = make_float4(o[0], o[1], o[2], o[3]);
        Cn[1] = make_float4(o[4], o[5], o[6], o[7]);
    } else {
        int g = __ldg(&batch[n]);
        float* dst = g_P + (size_t)g * DP + c0;
        unsigned long long p0 = (unsigned long long)__cvta_generic_to_global(dst);
        asm volatile("red.global.add.v4.f32 [%0], {%1,%2,%3,%4};"
                     :: "l"(p0), "f"(o[0]), "f"(o[1]), "f"(o[2]), "f"(o[3]) : "memory");
        unsigned long long p1 = (unsigned long long)__cvta_generic_to_global(dst + 4);
        asm volatile("red.global.add.v4.f32 [%0], {%1,%2,%3,%4};"
                     :: "l"(p1), "f"(o[4]), "f"(o[5]), "f"(o[6]), "f"(o[7]) : "memory");
    }
}

// ------------------------------------------------------------------
__device__ __forceinline__ int lbound(const int* b, int n, int v) {
    int lo = 0, hi = n;
    while (lo < hi) { int m = (lo + hi) >> 1; if (b[m] < v) lo = m + 1; else hi = m; }
    return lo;
}

__global__ void cntg_kernel(const int* __restrict__ batch) {
    int g = blockIdx.x * blockDim.x + threadIdx.x;
    if (g < N_GRAPHS)
        g_cntg[g] = lbound(batch, N_NODES, g + 1) - lbound(batch, N_NODES, g);
}

__global__ void divide_kernel(float* __restrict__ out) {
    int idx = blockIdx.x * blockDim.x + threadIdx.x;
    if (idx >= N_GRAPHS * D) return;
    int g = idx / D;
    int c = idx - g * D;
    float cnt = (float)g_cntg[g];
    out[idx] = g_P[(size_t)g * DP + c] / fmaxf(cnt, 1.0f);
}

// ------------------------------------------------------------------
extern "C" void kernel_launch(void* const* d_in, const int* in_sizes, int n_in,
                              void* d_out, int out_size) {
    const float* x     = (const float*)d_in[0];
    const int*   ei    = (const int*)d_in[1];
    const int*   batch = (const int*)d_in[2];
    const float* W1  = (const float*)d_in[3];
    const float* b1  = (const float*)d_in[4];
    const float* W2  = (const float*)d_in[5];
    const float* b2  = (const float*)d_in[6];
    const float* g1  = (const float*)d_in[7];
    const float* be1 = (const float*)d_in[8];
    const float* rm1 = (const float*)d_in[9];
    const float* rv1 = (const float*)d_in[10];
    const float* g2  = (const float*)d_in[11];
    const float* be2 = (const float*)d_in[12];
    const float* rm2 = (const float*)d_in[13];
    const float* rv2 = (const float*)d_in[14];
    float* out = (float*)d_out;

    __half* pA;
    float *pC, *pP1, *pP2;
    uint32_t *pW1t, *pW2t;
    cudaGetSymbolAddress((void**)&pA, g_A16);
    cudaGetSymbolAddress((void**)&pC, g_C);
    cudaGetSymbolAddress((void**)&pP1, g_post1);
    cudaGetSymbolAddress((void**)&pP2, g_post2);
    cudaGetSymbolAddress((void**)&pW1t, g_W1t);
    cudaGetSymbolAddress((void**)&pW2t, g_W2t);

    // side stream + fork/join events, created once (no device allocation)
    static cudaStream_t s_side = nullptr;
    static cudaEvent_t ev_fork = nullptr, ev_join = nullptr;
    if (!s_side) {
        cudaStreamCreateWithFlags(&s_side, cudaStreamNonBlocking);
        cudaEventCreateWithFlags(&ev_fork, cudaEventDisableTiming);
        cudaEventCreateWithFlags(&ev_join, cudaEventDisableTiming);
    }

    const int smem = 136 * 136 * (int)sizeof(uint32_t);          // 74 KB -> 3 blocks/SM
    cudaFuncSetAttribute((const void*)gemm_tc_kernel,
                         cudaFuncAttributeMaxDynamicSharedMemorySize, smem);

    const int TB = 256;
    const int gemm_blocks   = (N_NODES + 63) / 64;                // 782
    const int gather_blocks = (N_NODES * 32 + TB - 1) / TB;       // warp per node

    // ---- main stream: prep for gemm1 ----
    w_cvt_kernel<<<(136 * 136 + TB - 1) / TB, TB>>>(W1, pW1t);
    zero_fused_kernel<<<(N_GRAPHS * DP + TB - 1) / TB, TB>>>();
    count_deg_kernel<<<(N_EDGES + TB - 1) / TB, TB>>>(ei);

    // ---- fork: CSR build + misc on side stream, overlapped with gemm1 ----
    cudaEventRecord(ev_fork, 0);
    cudaStreamWaitEvent(s_side, ev_fork, 0);
    scan1_kernel<<<SCAN_NB, SCAN_B, 0, s_side>>>();
    scan2_kernel<<<1, 32, 0, s_side>>>();
    scan3_kernel<<<SCAN_NB, SCAN_B, 0, s_side>>>();
    fill_csr_kernel<<<(N_EDGES + TB - 1) / TB, TB, 0, s_side>>>(ei);
    w_cvt_kernel<<<(136 * 136 + TB - 1) / TB, TB, 0, s_side>>>(W2, pW2t);
    prep_post_kernel<<<1, DP, 0, s_side>>>(b1, g1, be1, rm1, rv1, pP1);
    prep_post_kernel<<<1, DP, 0, s_side>>>(b2, g2, be2, rm2, rv2, pP2);
    cntg_kernel<<<(N_GRAPHS + TB - 1) / TB, TB, 0, s_side>>>(batch);
    cudaEventRecord(ev_join, s_side);

    // ---- main stream: dinv + gemm1 (concurrent with side) ----
    dinv_kernel<<<(N_NODES + TB - 1) / TB, TB>>>();
    gemm_tc_kernel<<<gemm_blocks, TB, smem>>>(x, D, pW1t);

    // ---- join, then the serial tail ----
    cudaStreamWaitEvent(0, ev_join, 0);
    gather_post_kernel<<<gather_blocks, TB>>>(pA, pC, pP1, 0, batch);
    gemm_tc_kernel<<<gemm_blocks, TB, smem>>>(pC, DP, pW2t);
    gather_post_kernel<<<gather_blocks, TB>>>(pA, pC, pP2, 1, batch);
    divide_kernel<<<(N_GRAPHS * D + TB - 1) / TB, TB>>>(out);
}

// round 10
// speedup vs baseline: 1.0873x; 1.0116x over previous
#include <cuda_runtime.h>
#include <cuda_fp16.h>
#include <cstdint>

#define N_NODES 50000
#define N_EDGES 1600000
#define N_GRAPHS 2048
#define D 133
#define DP 136           // fp32 padded row (floats)
#define DPH 144          // fp16 padded row (halves) = 288B (9 sectors)
#define EPSV 1e-5f
#define SCAN_B 1024
#define SCAN_NB ((N_NODES + SCAN_B - 1) / SCAN_B)   // 49

// -------- scratch (static device globals; no runtime allocation) --------
__device__ __align__(16) __half g_A16[(size_t)N_NODES * DPH];  // gemm out, dinv-scaled, fp16
__device__ __align__(16) float  g_C[(size_t)N_NODES * DP];     // gather out / layer-2 input
__device__ __align__(16) float  g_P[(size_t)N_GRAPHS * DP];    // pool accumulator
__device__ __align__(16) uint32_t g_W2t[136 * 136];            // W2 tf32, padded
__device__ float g_dinv[N_NODES];
__device__ int   g_cnt[N_NODES];
__device__ int   g_off[N_NODES + 1];
__device__ int   g_cursor[N_NODES];
__device__ int   g_csr[N_EDGES];
__device__ int   g_bsum[SCAN_NB];
__device__ int   g_cntg[N_GRAPHS];
__device__ float g_post1[3 * DP];    // bias | s | t   (zero-padded)
__device__ float g_post2[3 * DP];

// ------------------------------------------------------------------
__global__ void zero_fused_kernel() {
    int i = blockIdx.x * blockDim.x + threadIdx.x;
    if (i < N_GRAPHS * DP) g_P[i] = 0.0f;
    if (i < N_NODES)       g_cnt[i] = 0;
}

__global__ void count_deg_kernel(const int* __restrict__ ei) {
    int e = blockIdx.x * blockDim.x + threadIdx.x;
    if (e < N_EDGES) atomicAdd(&g_cnt[__ldg(&ei[N_EDGES + e])], 1);
}

__global__ void dinv_kernel() {
    int i = blockIdx.x * blockDim.x + threadIdx.x;
    if (i < N_NODES) g_dinv[i] = rsqrtf((float)(g_cnt[i] + 1));   // +1 self-loop
}

// ---- 3-kernel exclusive scan of g_cnt -> g_off ----
__global__ void scan1_kernel() {
    __shared__ int sh[SCAN_B];
    int t = threadIdx.x;
    int i = blockIdx.x * SCAN_B + t;
    int v = (i < N_NODES) ? g_cnt[i] : 0;
    sh[t] = v;
    __syncthreads();
#pragma unroll
    for (int d = 1; d < SCAN_B; d <<= 1) {
        int x = (t >= d) ? sh[t - d] : 0;
        __syncthreads();
        sh[t] += x;
        __syncthreads();
    }
    if (i < N_NODES) g_off[i] = sh[t] - v;           // exclusive, local
    if (t == SCAN_B - 1) g_bsum[blockIdx.x] = sh[t];
}

__global__ void scan2_kernel() {
    if (threadIdx.x == 0) {
        int acc = 0;
        for (int b = 0; b < SCAN_NB; b++) {
            int v = g_bsum[b];
            g_bsum[b] = acc;
            acc += v;
        }
    }
}

__global__ void scan3_kernel() {
    int i = blockIdx.x * blockDim.x + threadIdx.x;
    if (i < N_NODES) {
        int o = g_off[i] + g_bsum[i / SCAN_B];
        g_off[i] = o;
        g_cursor[i] = o;
    }
    if (i == 0) g_off[N_NODES] = N_EDGES;
}

__global__ void fill_csr_kernel(const int* __restrict__ ei) {
    int e = blockIdx.x * blockDim.x + threadIdx.x;
    if (e < N_EDGES) {
        int r = __ldg(&ei[e]);
        int c = __ldg(&ei[N_EDGES + e]);
        int pos = atomicAdd(&g_cursor[c], 1);
        g_csr[pos] = r;
    }
}

// ---- per-layer fused BN constants: bias | s | t, zero-padded to DP ----
__global__ void prep_post_kernel(const float* __restrict__ bias, const float* __restrict__ gam,
                                 const float* __restrict__ beta, const float* __restrict__ rm,
                                 const float* __restrict__ rv, float* __restrict__ dst) {
    int c = threadIdx.x;
    if (c >= DP) return;
    float bb = 0.0f, ss = 0.0f, tt = 0.0f;
    if (c < D) {
        bb = bias[c];
        float sc = gam[c] * rsqrtf(rv[c] + EPSV);
        ss = sc;
        tt = beta[c] - rm[c] * sc;
    }
    dst[c] = bb; dst[DP + c] = ss; dst[2 * DP + c] = tt;
}

// ------------------------------------------------------------------
__device__ __forceinline__ uint32_t f2tf32(float f) {
    uint32_t r;
    asm("cvt.rna.tf32.f32 %0, %1;" : "=r"(r) : "f"(f));
    return r;
}

__global__ void w_cvt_kernel(const float* __restrict__ W, uint32_t* __restrict__ Wt) {
    int i = blockIdx.x * blockDim.x + threadIdx.x;
    if (i >= 136 * 136) return;
    int k = i / 136, n = i - k * 136;
    Wt[i] = (k < D && n < D) ? f2tf32(__ldg(&W[k * D + n])) : 0u;
}

__device__ __forceinline__ void mma_tf32(float* d,
                                         uint32_t a0, uint32_t a1, uint32_t a2, uint32_t a3,
                                         uint32_t b0, uint32_t b1) {
    asm volatile("mma.sync.aligned.m16n8k8.row.col.f32.tf32.tf32.f32 "
                 "{%0,%1,%2,%3}, {%4,%5,%6,%7}, {%8,%9}, {%0,%1,%2,%3};"
                 : "+f"(d[0]), "+f"(d[1]), "+f"(d[2]), "+f"(d[3])
                 : "r"(a0), "r"(a1), "r"(a2), "r"(a3), "r"(b0), "r"(b1));
}

// Tensor-core GEMM: g_A16[row] = fp16( dinv[row] * (X @ W) ).
// CVT=true: convert f32 W in-prologue (layer 1, no separate w_cvt launch).
// n-split: warp pair shares 16 rows; colhalf 0 -> n-tiles 0..8, 1 -> 9..16.
template <bool CVT>
__global__ __launch_bounds__(256)
void gemm_tc_kernel(const float* __restrict__ X, int ldx,
                    const float* __restrict__ Wf, const uint32_t* __restrict__ Wt) {
    extern __shared__ uint32_t ws[];         // [136][136] tf32 bits

    int tid  = threadIdx.x;
    int w    = tid >> 5;
    int lane = tid & 31;

    if (CVT) {
        int n = tid, k = 0;
        for (int i = tid; i < 136 * 136; i += 256) {
            ws[i] = (k < D && n < D) ? f2tf32(__ldg(&Wf[k * D + n])) : 0u;
            n += 256;
            while (n >= 136) { n -= 136; k++; }
        }
    } else {
        const uint4* src = (const uint4*)Wt;
        uint4* dst = (uint4*)ws;
#pragma unroll 5
        for (int i = tid; i < (136 * 136) / 4; i += 256) dst[i] = __ldg(&src[i]);
    }
    __syncthreads();

    const int r0 = lane >> 2;        // A row group / B n
    const int kc = lane & 3;         // A k within quad / B k
    const int colhalf = w & 1;
    const int ntBase = colhalf * 9;
    const int ntCnt  = 9 - colhalf;  // 9 or 8 tiles

    int rowbase = blockIdx.x * 64 + (w >> 1) * 16;
    int row0 = rowbase + r0;
    int row1 = row0 + 8;
    bool v0 = row0 < N_NODES;
    bool v1 = row1 < N_NODES;
    const float* X0 = X + (size_t)row0 * ldx;
    const float* X1 = X + (size_t)row1 * ldx;

    float acc[9][4];
#pragma unroll
    for (int j = 0; j < 9; j++)
#pragma unroll
        for (int q = 0; q < 4; q++) acc[j][q] = 0.0f;

    // ks 0..15: cols <= 127 < 133, no column predication needed
#pragma unroll 4
    for (int ks = 0; ks < 16; ks++) {
        int c0 = ks * 8 + kc;
        uint32_t a0 = v0 ? f2tf32(__ldg(X0 + c0)) : 0u;
        uint32_t a1 = v1 ? f2tf32(__ldg(X1 + c0)) : 0u;
        uint32_t a2 = v0 ? f2tf32(__ldg(X0 + c0 + 4)) : 0u;
        uint32_t a3 = v1 ? f2tf32(__ldg(X1 + c0 + 4)) : 0u;
        const uint32_t* wr0 = ws + (ks * 8 + kc) * 136 + r0 + ntBase * 8;
        const uint32_t* wr1 = wr0 + 4 * 136;
#pragma unroll
        for (int j = 0; j < 9; j++) {
            if (j < ntCnt)
                mma_tf32(acc[j], a0, a1, a2, a3, wr0[j * 8], wr1[j * 8]);
        }
    }
    {   // tail ks=16: c0 = 128+kc always valid; c1 = 132+kc valid only for kc==0
        int c0 = 128 + kc;
        bool pv = (kc == 0);
        uint32_t a0 = v0 ? f2tf32(__ldg(X0 + c0)) : 0u;
        uint32_t a1 = v1 ? f2tf32(__ldg(X1 + c0)) : 0u;
        uint32_t a2 = (v0 && pv) ? f2tf32(__ldg(X0 + 132)) : 0u;
        uint32_t a3 = (v1 && pv) ? f2tf32(__ldg(X1 + 132)) : 0u;
        const uint32_t* wr0 = ws + (128 + kc) * 136 + r0 + ntBase * 8;
        const uint32_t* wr1 = wr0 + 4 * 136;
#pragma unroll
        for (int j = 0; j < 9; j++) {
            if (j < ntCnt)
                mma_tf32(acc[j], a0, a1, a2, a3, wr0[j * 8], wr1[j * 8]);
        }
    }

    // epilogue: dinv scale -> fp16 half2 stores (cols 133..135 get 0 via W pads)
    float dv0 = v0 ? g_dinv[row0] : 0.0f;
    float dv1 = v1 ? g_dinv[row1] : 0.0f;
    int cb = 2 * kc;
#pragma unroll
    for (int j = 0; j < 9; j++) {
        if (j < ntCnt) {
            int c = (ntBase + j) * 8 + cb;
            if (v0)
                *(__half2*)(g_A16 + (size_t)row0 * DPH + c) =
                    __floats2half2_rn(dv0 * acc[j][0], dv0 * acc[j][1]);
            if (v1)
                *(__half2*)(g_A16 + (size_t)row1 * DPH + c) =
                    __floats2half2_rn(dv1 * acc[j][2], dv1 * acc[j][3]);
        }
    }
}

// ------------------------------------------------------------------
// Warp-per-node CSR gather, full-warp lanes: lane l accumulates cols 4l..4l+3
// (uint2 = 2 half2); lanes 0-1 also handle tail cols 128..135. fp32 accum.
__global__ __launch_bounds__(256)
void gather_post_kernel(const __half* __restrict__ A, float* __restrict__ Cout,
                        const float* __restrict__ post, int do_pool,
                        const int* __restrict__ batch) {
    int gw = (blockIdx.x * blockDim.x + threadIdx.x) >> 5;
    if (gw >= N_NODES) return;
    int lane = threadIdx.x & 31;
    int n = gw;

    int lo = __ldg(&g_off[n]);
    int hi = __ldg(&g_off[n + 1]);
    bool tl = lane < 2;

    float a0 = 0.f, a1 = 0.f, a2 = 0.f, a3 = 0.f;
    float t0 = 0.f, t1 = 0.f, t2 = 0.f, t3 = 0.f;

#define ACCUM(SJ) do {                                                        \
        const char* R = (const char*)(A + (size_t)(SJ) * DPH);                \
        uint2 m = __ldg((const uint2*)R + lane);                              \
        float2 f0 = __half22float2(*(const __half2*)&m.x);                    \
        float2 f1 = __half22float2(*(const __half2*)&m.y);                    \
        a0 += f0.x; a1 += f0.y; a2 += f1.x; a3 += f1.y;                       \
        if (tl) {                                                             \
            uint2 mt = __ldg((const uint2*)(R + 256) + lane);                 \
            float2 g0 = __half22float2(*(const __half2*)&mt.x);               \
            float2 g1 = __half22float2(*(const __half2*)&mt.y);               \
            t0 += g0.x; t1 += g0.y; t2 += g1.x; t3 += g1.y;                   \
        }                                                                     \
    } while (0)

    ACCUM(n);   // self-loop term

    int e = lo;
    for (; e + 32 <= hi; e += 32) {
        int src = __ldg(&g_csr[e + lane]);
#pragma unroll 4
        for (int j = 0; j < 32; j++) {
            int sj = __shfl_sync(0xffffffffu, src, j);
            ACCUM(sj);
        }
    }
    for (; e < hi; e++) {
        int sj = __ldg(&g_csr[e]);
        ACCUM(sj);
    }
#undef ACCUM

    float dv = __ldg(&g_dinv[n]);
    const float* bb = post;
    const float* ss = post + DP;
    const float* tt = post + 2 * DP;

    int c0 = 4 * lane;
    float4 o;
    o.x = fmaf(fmaxf(fmaf(dv, a0, __ldg(&bb[c0 + 0])), 0.f), __ldg(&ss[c0 + 0]), __ldg(&tt[c0 + 0]));
    o.y = fmaf(fmaxf(fmaf(dv, a1, __ldg(&bb[c0 + 1])), 0.f), __ldg(&ss[c0 + 1]), __ldg(&tt[c0 + 1]));
    o.z = fmaf(fmaxf(fmaf(dv, a2, __ldg(&bb[c0 + 2])), 0.f), __ldg(&ss[c0 + 2]), __ldg(&tt[c0 + 2]));
    o.w = fmaf(fmaxf(fmaf(dv, a3, __ldg(&bb[c0 + 3])), 0.f), __ldg(&ss[c0 + 3]), __ldg(&tt[c0 + 3]));
    float4 ot = make_float4(0.f, 0.f, 0.f, 0.f);
    if (tl) {
        int ct = 128 + 4 * lane;
        ot.x = fmaf(fmaxf(fmaf(dv, t0, __ldg(&bb[ct + 0])), 0.f), __ldg(&ss[ct + 0]), __ldg(&tt[ct + 0]));
        ot.y = fmaf(fmaxf(fmaf(dv, t1, __ldg(&bb[ct + 1])), 0.f), __ldg(&ss[ct + 1]), __ldg(&tt[ct + 1]));
        ot.z = fmaf(fmaxf(fmaf(dv, t2, __ldg(&bb[ct + 2])), 0.f), __ldg(&ss[ct + 2]), __ldg(&tt[ct + 2]));
        ot.w = fmaf(fmaxf(fmaf(dv, t3, __ldg(&bb[ct + 3])), 0.f), __ldg(&ss[ct + 3]), __ldg(&tt[ct + 3]));
    }

    if (!do_pool) {
        *(float4*)(Cout + (size_t)n * DP + c0) = o;
        if (tl) *(float4*)(Cout + (size_t)n * DP + 128 + 4 * lane) = ot;
    } else {
        int g = __ldg(&batch[n]);
        float* dst = g_P + (size_t)g * DP + c0;
        unsigned long long p0 = (unsigned long long)__cvta_generic_to_global(dst);
        asm volatile("red.global.add.v4.f32 [%0], {%1,%2,%3,%4};"
                     :: "l"(p0), "f"(o.x), "f"(o.y), "f"(o.z), "f"(o.w) : "memory");
        if (tl) {
            float* dt = g_P + (size_t)g * DP + 128 + 4 * lane;
            unsigned long long p1 = (unsigned long long)__cvta_generic_to_global(dt);
            asm volatile("red.global.add.v4.f32 [%0], {%1,%2,%3,%4};"
                         :: "l"(p1), "f"(ot.x), "f"(ot.y), "f"(ot.z), "f"(ot.w) : "memory");
        }
    }
}

// ------------------------------------------------------------------
__device__ __forceinline__ int lbound(const int* b, int n, int v) {
    int lo = 0, hi = n;
    while (lo < hi) { int m = (lo + hi) >> 1; if (b[m] < v) lo = m + 1; else hi = m; }
    return lo;
}

__global__ void cntg_kernel(const int* __restrict__ batch) {
    int g = blockIdx.x * blockDim.x + threadIdx.x;
    if (g < N_GRAPHS)
        g_cntg[g] = lbound(batch, N_NODES, g + 1) - lbound(batch, N_NODES, g);
}

__global__ void divide_kernel(float* __restrict__ out) {
    int idx = blockIdx.x * blockDim.x + threadIdx.x;
    if (idx >= N_GRAPHS * D) return;
    int g = idx / D;
    int c = idx - g * D;
    float cnt = (float)g_cntg[g];
    out[idx] = g_P[(size_t)g * DP + c] / fmaxf(cnt, 1.0f);
}

// ------------------------------------------------------------------
extern "C" void kernel_launch(void* const* d_in, const int* in_sizes, int n_in,
                              void* d_out, int out_size) {
    const float* x     = (const float*)d_in[0];
    const int*   ei    = (const int*)d_in[1];
    const int*   batch = (const int*)d_in[2];
    const float* W1  = (const float*)d_in[3];
    const float* b1  = (const float*)d_in[4];
    const float* W2  = (const float*)d_in[5];
    const float* b2  = (const float*)d_in[6];
    const float* g1  = (const float*)d_in[7];
    const float* be1 = (const float*)d_in[8];
    const float* rm1 = (const float*)d_in[9];
    const float* rv1 = (const float*)d_in[10];
    const float* g2  = (const float*)d_in[11];
    const float* be2 = (const float*)d_in[12];
    const float* rm2 = (const float*)d_in[13];
    const float* rv2 = (const float*)d_in[14];
    float* out = (float*)d_out;

    __half* pA;
    float *pC, *pP1, *pP2;
    uint32_t* pW2t;
    cudaGetSymbolAddress((void**)&pA, g_A16);
    cudaGetSymbolAddress((void**)&pC, g_C);
    cudaGetSymbolAddress((void**)&pP1, g_post1);
    cudaGetSymbolAddress((void**)&pP2, g_post2);
    cudaGetSymbolAddress((void**)&pW2t, g_W2t);

    // side stream + fork/join events, created once (no device allocation)
    static cudaStream_t s_side = nullptr;
    static cudaEvent_t ev_fork = nullptr, ev_join = nullptr;
    if (!s_side) {
        cudaStreamCreateWithFlags(&s_side, cudaStreamNonBlocking);
        cudaEventCreateWithFlags(&ev_fork, cudaEventDisableTiming);
        cudaEventCreateWithFlags(&ev_join, cudaEventDisableTiming);
    }

    const int smem = 136 * 136 * (int)sizeof(uint32_t);          // 74 KB -> 3 blocks/SM
    cudaFuncSetAttribute((const void*)gemm_tc_kernel<true>,
                         cudaFuncAttributeMaxDynamicSharedMemorySize, smem);
    cudaFuncSetAttribute((const void*)gemm_tc_kernel<false>,
                         cudaFuncAttributeMaxDynamicSharedMemorySize, smem);

    const int TB = 256;
    const int gemm_blocks   = (N_NODES + 63) / 64;                // 782
    const int gather_blocks = (N_NODES * 32 + TB - 1) / TB;       // warp per node

    // ---- main: zero(1), count(2), dinv(3), gemm1(4) -> ncu captures gemm1 ----
    zero_fused_kernel<<<(N_GRAPHS * DP + TB - 1) / TB, TB>>>();
    count_deg_kernel<<<(N_EDGES + TB - 1) / TB, TB>>>(ei);
    cudaEventRecord(ev_fork, 0);
    dinv_kernel<<<(N_NODES + TB - 1) / TB, TB>>>();
    gemm_tc_kernel<true><<<gemm_blocks, TB, smem>>>(x, D, W1, nullptr);

    // ---- side: CSR build + misc, overlapped with gemm1 ----
    cudaStreamWaitEvent(s_side, ev_fork, 0);
    scan1_kernel<<<SCAN_NB, SCAN_B, 0, s_side>>>();
    scan2_kernel<<<1, 32, 0, s_side>>>();
    scan3_kernel<<<SCAN_NB, SCAN_B, 0, s_side>>>();
    fill_csr_kernel<<<(N_EDGES + TB - 1) / TB, TB, 0, s_side>>>(ei);
    w_cvt_kernel<<<(136 * 136 + TB - 1) / TB, TB, 0, s_side>>>(W2, pW2t);
    prep_post_kernel<<<1, DP, 0, s_side>>>(b1, g1, be1, rm1, rv1, pP1);
    prep_post_kernel<<<1, DP, 0, s_side>>>(b2, g2, be2, rm2, rv2, pP2);
    cntg_kernel<<<(N_GRAPHS + TB - 1) / TB, TB, 0, s_side>>>(batch);
    cudaEventRecord(ev_join, s_side);

    // ---- join, then the serial tail ----
    cudaStreamWaitEvent(0, ev_join, 0);
    gather_post_kernel<<<gather_blocks, TB>>>(pA, pC, pP1, 0, batch);
    gemm_tc_kernel<false><<<gemm_blocks, TB, smem>>>(pC, DP, nullptr, pW2t);
    gather_post_kernel<<<gather_blocks, TB>>>(pA, pC, pP2, 1, batch);
    divide_kernel<<<(N_GRAPHS * D + TB - 1) / TB, TB>>>(out);
}

// round 11
// speedup vs baseline: 1.0960x; 1.0079x over previous
#include <cuda_runtime.h>
#include <cuda_fp16.h>
#include <cstdint>

#define N_NODES 50000
#define N_EDGES 1600000
#define N_GRAPHS 2048
#define D 133
#define DP 136           // fp32 padded row (floats)
#define DPH 144          // fp16 padded row (halves) = 288B (9 sectors)
#define EPSV 1e-5f
#define SCAN_B 1024
#define SCAN_NB ((N_NODES + SCAN_B - 1) / SCAN_B)   // 49

// -------- scratch (static device globals; no runtime allocation) --------
__device__ __align__(16) __half g_A16[(size_t)N_NODES * DPH];  // gemm out, dinv-scaled, fp16
__device__ __align__(16) float  g_C[(size_t)N_NODES * DP];     // gather out / layer-2 input
__device__ __align__(16) float  g_P[(size_t)N_GRAPHS * DP];    // pool accumulator
__device__ __align__(16) uint32_t g_W2t[136 * 136];            // W2 tf32, padded
__device__ float g_dinv[N_NODES];
__device__ int   g_cnt[N_NODES];
__device__ int   g_off[N_NODES + 1];
__device__ int   g_cursor[N_NODES];
__device__ int   g_csr[N_EDGES];
__device__ int   g_bsum[SCAN_NB];
__device__ int   g_cntg[N_GRAPHS];
__device__ float g_post1[3 * DP];    // bias | s | t   (zero-padded)
__device__ float g_post2[3 * DP];

// ------------------------------------------------------------------
__global__ void zero_fused_kernel() {
    int i = blockIdx.x * blockDim.x + threadIdx.x;
    if (i < N_GRAPHS * DP) g_P[i] = 0.0f;
    if (i < N_NODES)       g_cnt[i] = 0;
}

__global__ void count_deg_kernel(const int* __restrict__ ei) {
    int e = blockIdx.x * blockDim.x + threadIdx.x;
    if (e < N_EDGES) atomicAdd(&g_cnt[__ldg(&ei[N_EDGES + e])], 1);
}

__global__ void dinv_kernel() {
    int i = blockIdx.x * blockDim.x + threadIdx.x;
    if (i < N_NODES) g_dinv[i] = rsqrtf((float)(g_cnt[i] + 1));   // +1 self-loop
}

// ---- 3-kernel exclusive scan of g_cnt -> g_off ----
__global__ void scan1_kernel() {
    __shared__ int sh[SCAN_B];
    int t = threadIdx.x;
    int i = blockIdx.x * SCAN_B + t;
    int v = (i < N_NODES) ? g_cnt[i] : 0;
    sh[t] = v;
    __syncthreads();
#pragma unroll
    for (int d = 1; d < SCAN_B; d <<= 1) {
        int x = (t >= d) ? sh[t - d] : 0;
        __syncthreads();
        sh[t] += x;
        __syncthreads();
    }
    if (i < N_NODES) g_off[i] = sh[t] - v;           // exclusive, local
    if (t == SCAN_B - 1) g_bsum[blockIdx.x] = sh[t];
}

__global__ void scan2_kernel() {
    if (threadIdx.x == 0) {
        int acc = 0;
        for (int b = 0; b < SCAN_NB; b++) {
            int v = g_bsum[b];
            g_bsum[b] = acc;
            acc += v;
        }
    }
}

__global__ void scan3_kernel() {
    int i = blockIdx.x * blockDim.x + threadIdx.x;
    if (i < N_NODES) {
        int o = g_off[i] + g_bsum[i / SCAN_B];
        g_off[i] = o;
        g_cursor[i] = o;
    }
    if (i == 0) g_off[N_NODES] = N_EDGES;
}

__global__ void fill_csr_kernel(const int* __restrict__ ei) {
    int e = blockIdx.x * blockDim.x + threadIdx.x;
    if (e < N_EDGES) {
        int r = __ldg(&ei[e]);
        int c = __ldg(&ei[N_EDGES + e]);
        int pos = atomicAdd(&g_cursor[c], 1);
        g_csr[pos] = r;
    }
}

// ---- per-layer fused BN constants: bias | s | t, zero-padded to DP ----
__global__ void prep_post_kernel(const float* __restrict__ bias, const float* __restrict__ gam,
                                 const float* __restrict__ beta, const float* __restrict__ rm,
                                 const float* __restrict__ rv, float* __restrict__ dst) {
    int c = threadIdx.x;
    if (c >= DP) return;
    float bb = 0.0f, ss = 0.0f, tt = 0.0f;
    if (c < D) {
        bb = bias[c];
        float sc = gam[c] * rsqrtf(rv[c] + EPSV);
        ss = sc;
        tt = beta[c] - rm[c] * sc;
    }
    dst[c] = bb; dst[DP + c] = ss; dst[2 * DP + c] = tt;
}

// ------------------------------------------------------------------
__device__ __forceinline__ uint32_t f2tf32(float f) {
    uint32_t r;
    asm("cvt.rna.tf32.f32 %0, %1;" : "=r"(r) : "f"(f));
    return r;
}

__global__ void w_cvt_kernel(const float* __restrict__ W, uint32_t* __restrict__ Wt) {
    int i = blockIdx.x * blockDim.x + threadIdx.x;
    if (i >= 136 * 136) return;
    int k = i / 136, n = i - k * 136;
    Wt[i] = (k < D && n < D) ? f2tf32(__ldg(&W[k * D + n])) : 0u;
}

__device__ __forceinline__ void mma_tf32(float* d,
                                         uint32_t a0, uint32_t a1, uint32_t a2, uint32_t a3,
                                         uint32_t b0, uint32_t b1) {
    asm volatile("mma.sync.aligned.m16n8k8.row.col.f32.tf32.tf32.f32 "
                 "{%0,%1,%2,%3}, {%4,%5,%6,%7}, {%8,%9}, {%0,%1,%2,%3};"
                 : "+f"(d[0]), "+f"(d[1]), "+f"(d[2]), "+f"(d[3])
                 : "r"(a0), "r"(a1), "r"(a2), "r"(a3), "r"(b0), "r"(b1));
}

// Tensor-core GEMM: g_A16[row] = fp16( dinv[row] * (X @ W) ).
// CVT=true: convert f32 W in-prologue (layer 1). n-split: warp pair shares
// 16 rows; colhalf 0 -> n-tiles 0..8, 1 -> 9..16. A loads software-pipelined.
template <bool CVT>
__global__ __launch_bounds__(256, 3)
void gemm_tc_kernel(const float* __restrict__ X, int ldx,
                    const float* __restrict__ Wf, const uint32_t* __restrict__ Wt) {
    extern __shared__ uint32_t ws[];         // [136][136] tf32 bits

    int tid  = threadIdx.x;
    int w    = tid >> 5;
    int lane = tid & 31;

    if (CVT) {
        int k = tid / 136;               // FIXED: proper (k, n) decomposition
        int n = tid - k * 136;
        for (int i = tid; i < 136 * 136; i += 256) {
            ws[i] = (k < D && n < D) ? f2tf32(__ldg(&Wf[k * D + n])) : 0u;
            n += 256;
            while (n >= 136) { n -= 136; k++; }
        }
    } else {
        const uint4* src = (const uint4*)Wt;
        uint4* dst = (uint4*)ws;
#pragma unroll 5
        for (int i = tid; i < (136 * 136) / 4; i += 256) dst[i] = __ldg(&src[i]);
    }
    __syncthreads();

    const int r0 = lane >> 2;        // A row group / B n
    const int kc = lane & 3;         // A k within quad / B k
    const int colhalf = w & 1;
    const int ntBase = colhalf * 9;
    const int ntCnt  = 9 - colhalf;  // 9 or 8 tiles

    int rowbase = blockIdx.x * 64 + (w >> 1) * 16;
    int row0 = rowbase + r0;
    int row1 = row0 + 8;
    bool v0 = row0 < N_NODES;
    bool v1 = row1 < N_NODES;
    const float* X0 = X + (size_t)row0 * ldx;
    const float* X1 = X + (size_t)row1 * ldx;

    float acc[9][4];
#pragma unroll
    for (int j = 0; j < 9; j++)
#pragma unroll
        for (int q = 0; q < 4; q++) acc[j][q] = 0.0f;

    // software-pipelined mainloop: prefetch ks+1 A-values during ks MMAs.
    // ks 0..15: cols <= 131 < 133 (no col predication). ks 16 tail:
    // c0 = 128+kc always valid, c1 = 132+kc only for kc==0.
    uint32_t a0, a1, a2, a3;
    {
        a0 = v0 ? f2tf32(__ldg(X0 + kc)) : 0u;
        a1 = v1 ? f2tf32(__ldg(X1 + kc)) : 0u;
        a2 = v0 ? f2tf32(__ldg(X0 + kc + 4)) : 0u;
        a3 = v1 ? f2tf32(__ldg(X1 + kc + 4)) : 0u;
    }
    const uint32_t* wr = ws + kc * 136 + r0 + ntBase * 8;

#pragma unroll
    for (int ks = 0; ks < 17; ks++) {
        uint32_t na0 = 0, na1 = 0, na2 = 0, na3 = 0;
        if (ks < 16) {
            int c0 = (ks + 1) * 8 + kc;
            bool pv = (ks + 1 < 16) || (kc == 0);
            na0 = v0 ? f2tf32(__ldg(X0 + c0)) : 0u;
            na1 = v1 ? f2tf32(__ldg(X1 + c0)) : 0u;
            na2 = (v0 && pv) ? f2tf32(__ldg(X0 + c0 + 4)) : 0u;
            na3 = (v1 && pv) ? f2tf32(__ldg(X1 + c0 + 4)) : 0u;
        }
#pragma unroll
        for (int j = 0; j < 9; j++) {
            if (j < ntCnt)
                mma_tf32(acc[j], a0, a1, a2, a3, wr[j * 8], wr[j * 8 + 4 * 136]);
        }
        wr += 8 * 136;
        a0 = na0; a1 = na1; a2 = na2; a3 = na3;
    }

    // epilogue: dinv scale -> fp16 half2 stores (cols 133..135 get 0 via W pads)
    float dv0 = v0 ? g_dinv[row0] : 0.0f;
    float dv1 = v1 ? g_dinv[row1] : 0.0f;
    int cb = 2 * kc;
#pragma unroll
    for (int j = 0; j < 9; j++) {
        if (j < ntCnt) {
            int c = (ntBase + j) * 8 + cb;
            if (v0)
                *(__half2*)(g_A16 + (size_t)row0 * DPH + c) =
                    __floats2half2_rn(dv0 * acc[j][0], dv0 * acc[j][1]);
            if (v1)
                *(__half2*)(g_A16 + (size_t)row1 * DPH + c) =
                    __floats2half2_rn(dv1 * acc[j][2], dv1 * acc[j][3]);
        }
    }
}

// ------------------------------------------------------------------
// Warp-per-node CSR gather, full-warp lanes: lane l accumulates cols 4l..4l+3
// (uint2 = 2 half2); lanes 0-1 also handle tail cols 128..135. fp32 accum.
__global__ __launch_bounds__(256)
void gather_post_kernel(const __half* __restrict__ A, float* __restrict__ Cout,
                        const float* __restrict__ post, int do_pool,
                        const int* __restrict__ batch) {
    int gw = (blockIdx.x * blockDim.x + threadIdx.x) >> 5;
    if (gw >= N_NODES) return;
    int lane = threadIdx.x & 31;
    int n = gw;

    int lo = __ldg(&g_off[n]);
    int hi = __ldg(&g_off[n + 1]);
    bool tl = lane < 2;

    float a0 = 0.f, a1 = 0.f, a2 = 0.f, a3 = 0.f;
    float t0 = 0.f, t1 = 0.f, t2 = 0.f, t3 = 0.f;

#define ACCUM(SJ) do {                                                        \
        const char* R = (const char*)(A + (size_t)(SJ) * DPH);                \
        uint2 m = __ldg((const uint2*)R + lane);                              \
        float2 f0 = __half22float2(*(const __half2*)&m.x);                    \
        float2 f1 = __half22float2(*(const __half2*)&m.y);                    \
        a0 += f0.x; a1 += f0.y; a2 += f1.x; a3 += f1.y;                       \
        if (tl) {                                                             \
            uint2 mt = __ldg((const uint2*)(R + 256) + lane);                 \
            float2 g0 = __half22float2(*(const __half2*)&mt.x);               \
            float2 g1 = __half22float2(*(const __half2*)&mt.y);               \
            t0 += g0.x; t1 += g0.y; t2 += g1.x; t3 += g1.y;                   \
        }                                                                     \
    } while (0)

    ACCUM(n);   // self-loop term

    int e = lo;
    for (; e + 32 <= hi; e += 32) {
        int src = __ldg(&g_csr[e + lane]);
#pragma unroll 4
        for (int j = 0; j < 32; j++) {
            int sj = __shfl_sync(0xffffffffu, src, j);
            ACCUM(sj);
        }
    }
    for (; e < hi; e++) {
        int sj = __ldg(&g_csr[e]);
        ACCUM(sj);
    }
#undef ACCUM

    float dv = __ldg(&g_dinv[n]);
    const float* bb = post;
    const float* ss = post + DP;
    const float* tt = post + 2 * DP;

    int c0 = 4 * lane;
    float4 o;
    o.x = fmaf(fmaxf(fmaf(dv, a0, __ldg(&bb[c0 + 0])), 0.f), __ldg(&ss[c0 + 0]), __ldg(&tt[c0 + 0]));
    o.y = fmaf(fmaxf(fmaf(dv, a1, __ldg(&bb[c0 + 1])), 0.f), __ldg(&ss[c0 + 1]), __ldg(&tt[c0 + 1]));
    o.z = fmaf(fmaxf(fmaf(dv, a2, __ldg(&bb[c0 + 2])), 0.f), __ldg(&ss[c0 + 2]), __ldg(&tt[c0 + 2]));
    o.w = fmaf(fmaxf(fmaf(dv, a3, __ldg(&bb[c0 + 3])), 0.f), __ldg(&ss[c0 + 3]), __ldg(&tt[c0 + 3]));
    float4 ot = make_float4(0.f, 0.f, 0.f, 0.f);
    if (tl) {
        int ct = 128 + 4 * lane;
        ot.x = fmaf(fmaxf(fmaf(dv, t0, __ldg(&bb[ct + 0])), 0.f), __ldg(&ss[ct + 0]), __ldg(&tt[ct + 0]));
        ot.y = fmaf(fmaxf(fmaf(dv, t1, __ldg(&bb[ct + 1])), 0.f), __ldg(&ss[ct + 1]), __ldg(&tt[ct + 1]));
        ot.z = fmaf(fmaxf(fmaf(dv, t2, __ldg(&bb[ct + 2])), 0.f), __ldg(&ss[ct + 2]), __ldg(&tt[ct + 2]));
        ot.w = fmaf(fmaxf(fmaf(dv, t3, __ldg(&bb[ct + 3])), 0.f), __ldg(&ss[ct + 3]), __ldg(&tt[ct + 3]));
    }

    if (!do_pool) {
        *(float4*)(Cout + (size_t)n * DP + c0) = o;
        if (tl) *(float4*)(Cout + (size_t)n * DP + 128 + 4 * lane) = ot;
    } else {
        int g = __ldg(&batch[n]);
        float* dst = g_P + (size_t)g * DP + c0;
        unsigned long long p0 = (unsigned long long)__cvta_generic_to_global(dst);
        asm volatile("red.global.add.v4.f32 [%0], {%1,%2,%3,%4};"
                     :: "l"(p0), "f"(o.x), "f"(o.y), "f"(o.z), "f"(o.w) : "memory");
        if (tl) {
            float* dt = g_P + (size_t)g * DP + 128 + 4 * lane;
            unsigned long long p1 = (unsigned long long)__cvta_generic_to_global(dt);
            asm volatile("red.global.add.v4.f32 [%0], {%1,%2,%3,%4};"
                         :: "l"(p1), "f"(ot.x), "f"(ot.y), "f"(ot.z), "f"(ot.w) : "memory");
        }
    }
}

// ------------------------------------------------------------------
__device__ __forceinline__ int lbound(const int* b, int n, int v) {
    int lo = 0, hi = n;
    while (lo < hi) { int m = (lo + hi) >> 1; if (b[m] < v) lo = m + 1; else hi = m; }
    return lo;
}

__global__ void cntg_kernel(const int* __restrict__ batch) {
    int g = blockIdx.x * blockDim.x + threadIdx.x;
    if (g < N_GRAPHS)
        g_cntg[g] = lbound(batch, N_NODES, g + 1) - lbound(batch, N_NODES, g);
}

__global__ void divide_kernel(float* __restrict__ out) {
    int idx = blockIdx.x * blockDim.x + threadIdx.x;
    if (idx >= N_GRAPHS * D) return;
    int g = idx / D;
    int c = idx - g * D;
    float cnt = (float)g_cntg[g];
    out[idx] = g_P[(size_t)g * DP + c] / fmaxf(cnt, 1.0f);
}

// ------------------------------------------------------------------
extern "C" void kernel_launch(void* const* d_in, const int* in_sizes, int n_in,
                              void* d_out, int out_size) {
    const float* x     = (const float*)d_in[0];
    const int*   ei    = (const int*)d_in[1];
    const int*   batch = (const int*)d_in[2];
    const float* W1  = (const float*)d_in[3];
    const float* b1  = (const float*)d_in[4];
    const float* W2  = (const float*)d_in[5];
    const float* b2  = (const float*)d_in[6];
    const float* g1  = (const float*)d_in[7];
    const float* be1 = (const float*)d_in[8];
    const float* rm1 = (const float*)d_in[9];
    const float* rv1 = (const float*)d_in[10];
    const float* g2  = (const float*)d_in[11];
    const float* be2 = (const float*)d_in[12];
    const float* rm2 = (const float*)d_in[13];
    const float* rv2 = (const float*)d_in[14];
    float* out = (float*)d_out;

    __half* pA;
    float *pC, *pP1, *pP2;
    uint32_t* pW2t;
    cudaGetSymbolAddress((void**)&pA, g_A16);
    cudaGetSymbolAddress((void**)&pC, g_C);
    cudaGetSymbolAddress((void**)&pP1, g_post1);
    cudaGetSymbolAddress((void**)&pP2, g_post2);
    cudaGetSymbolAddress((void**)&pW2t, g_W2t);

    // side stream + fork/join events, created once (no device allocation)
    static cudaStream_t s_side = nullptr;
    static cudaEvent_t ev_fork = nullptr, ev_join = nullptr;
    if (!s_side) {
        cudaStreamCreateWithFlags(&s_side, cudaStreamNonBlocking);
        cudaEventCreateWithFlags(&ev_fork, cudaEventDisableTiming);
        cudaEventCreateWithFlags(&ev_join, cudaEventDisableTiming);
    }

    const int smem = 136 * 136 * (int)sizeof(uint32_t);          // 74 KB -> 3 blocks/SM
    cudaFuncSetAttribute((const void*)gemm_tc_kernel<true>,
                         cudaFuncAttributeMaxDynamicSharedMemorySize, smem);
    cudaFuncSetAttribute((const void*)gemm_tc_kernel<false>,
                         cudaFuncAttributeMaxDynamicSharedMemorySize, smem);

    const int TB = 256;
    const int gemm_blocks   = (N_NODES + 63) / 64;                // 782
    const int gather_blocks = (N_NODES * 32 + TB - 1) / TB;       // warp per node

    // ---- main: zero(1), count(2), dinv(3), gemm1(4) -> ncu captures gemm1 ----
    zero_fused_kernel<<<(N_GRAPHS * DP + TB - 1) / TB, TB>>>();
    count_deg_kernel<<<(N_EDGES + TB - 1) / TB, TB>>>(ei);
    cudaEventRecord(ev_fork, 0);
    dinv_kernel<<<(N_NODES + TB - 1) / TB, TB>>>();
    gemm_tc_kernel<true><<<gemm_blocks, TB, smem>>>(x, D, W1, nullptr);

    // ---- side: CSR build + misc, overlapped with gemm1 ----
    cudaStreamWaitEvent(s_side, ev_fork, 0);
    scan1_kernel<<<SCAN_NB, SCAN_B, 0, s_side>>>();
    scan2_kernel<<<1, 32, 0, s_side>>>();
    scan3_kernel<<<SCAN_NB, SCAN_B, 0, s_side>>>();
    fill_csr_kernel<<<(N_EDGES + TB - 1) / TB, TB, 0, s_side>>>(ei);
    w_cvt_kernel<<<(136 * 136 + TB - 1) / TB, TB, 0, s_side>>>(W2, pW2t);
    prep_post_kernel<<<1, DP, 0, s_side>>>(b1, g1, be1, rm1, rv1, pP1);
    prep_post_kernel<<<1, DP, 0, s_side>>>(b2, g2, be2, rm2, rv2, pP2);
    cntg_kernel<<<(N_GRAPHS + TB - 1) / TB, TB, 0, s_side>>>(batch);
    cudaEventRecord(ev_join, s_side);

    // ---- join, then the serial tail ----
    cudaStreamWaitEvent(0, ev_join, 0);
    gather_post_kernel<<<gather_blocks, TB>>>(pA, pC, pP1, 0, batch);
    gemm_tc_kernel<false><<<gemm_blocks, TB, smem>>>(pC, DP, nullptr, pW2t);
    gather_post_kernel<<<gather_blocks, TB>>>(pA, pC, pP2, 1, batch);
    divide_kernel<<<(N_GRAPHS * D + TB - 1) / TB, TB>>>(out);
}

// round 12
// speedup vs baseline: 1.2230x; 1.1160x over previous
#include <cuda_runtime.h>
#include <cuda_fp16.h>
#include <cstdint>

#define N_NODES 50000
#define N_EDGES 1600000
#define N_GRAPHS 2048
#define D 133
#define DP 136           // fp32 padded row (floats)
#define DPH 144          // fp16 padded row (halves) = 288B (9 sectors)
#define WKS 152          // W smem k-stride in halves (bank-conflict-free)
#define EPSV 1e-5f
#define SCAN_B 1024
#define SCAN_NB ((N_NODES + SCAN_B - 1) / SCAN_B)   // 49

// -------- scratch (static device globals; no runtime allocation) --------
__device__ __align__(16) __half g_A16[(size_t)N_NODES * DPH];  // gemm out, dinv-scaled, fp16
__device__ __align__(16) float  g_C[(size_t)N_NODES * DP];     // gather out / layer-2 input
__device__ __align__(16) float  g_P[(size_t)N_GRAPHS * DP];    // pool accumulator
__device__ __align__(16) __half g_W2th[136 * WKS];             // W2 fp16, [n][k] transposed
__device__ float g_dinv[N_NODES];
__device__ int   g_cnt[N_NODES];
__device__ int   g_off[N_NODES + 1];
__device__ int   g_cursor[N_NODES];
__device__ int   g_csr[N_EDGES];
__device__ int   g_bsum[SCAN_NB];
__device__ int   g_cntg[N_GRAPHS];
__device__ float g_post1[3 * DP];    // bias | s | t   (zero-padded)
__device__ float g_post2[3 * DP];

// ------------------------------------------------------------------
__global__ void zero_fused_kernel() {
    int i = blockIdx.x * blockDim.x + threadIdx.x;
    if (i < N_GRAPHS * DP) g_P[i] = 0.0f;
    if (i < N_NODES)       g_cnt[i] = 0;
}

__global__ void count_deg_kernel(const int* __restrict__ ei) {
    int e = blockIdx.x * blockDim.x + threadIdx.x;
    if (e < N_EDGES) atomicAdd(&g_cnt[__ldg(&ei[N_EDGES + e])], 1);
}

__global__ void dinv_kernel() {
    int i = blockIdx.x * blockDim.x + threadIdx.x;
    if (i < N_NODES) g_dinv[i] = rsqrtf((float)(g_cnt[i] + 1));   // +1 self-loop
}

// ---- 3-kernel exclusive scan of g_cnt -> g_off ----
__global__ void scan1_kernel() {
    __shared__ int sh[SCAN_B];
    int t = threadIdx.x;
    int i = blockIdx.x * SCAN_B + t;
    int v = (i < N_NODES) ? g_cnt[i] : 0;
    sh[t] = v;
    __syncthreads();
#pragma unroll
    for (int d = 1; d < SCAN_B; d <<= 1) {
        int x = (t >= d) ? sh[t - d] : 0;
        __syncthreads();
        sh[t] += x;
        __syncthreads();
    }
    if (i < N_NODES) g_off[i] = sh[t] - v;           // exclusive, local
    if (t == SCAN_B - 1) g_bsum[blockIdx.x] = sh[t];
}

__global__ void scan2_kernel() {
    if (threadIdx.x == 0) {
        int acc = 0;
        for (int b = 0; b < SCAN_NB; b++) {
            int v = g_bsum[b];
            g_bsum[b] = acc;
            acc += v;
        }
    }
}

__global__ void scan3_kernel() {
    int i = blockIdx.x * blockDim.x + threadIdx.x;
    if (i < N_NODES) {
        int o = g_off[i] + g_bsum[i / SCAN_B];
        g_off[i] = o;
        g_cursor[i] = o;
    }
    if (i == 0) g_off[N_NODES] = N_EDGES;
}

__global__ void fill_csr_kernel(const int* __restrict__ ei) {
    int e = blockIdx.x * blockDim.x + threadIdx.x;
    if (e < N_EDGES) {
        int r = __ldg(&ei[e]);
        int c = __ldg(&ei[N_EDGES + e]);
        int pos = atomicAdd(&g_cursor[c], 1);
        g_csr[pos] = r;
    }
}

// ---- per-layer fused BN constants: bias | s | t, zero-padded to DP ----
__global__ void prep_post_kernel(const float* __restrict__ bias, const float* __restrict__ gam,
                                 const float* __restrict__ beta, const float* __restrict__ rm,
                                 const float* __restrict__ rv, float* __restrict__ dst) {
    int c = threadIdx.x;
    if (c >= DP) return;
    float bb = 0.0f, ss = 0.0f, tt = 0.0f;
    if (c < D) {
        bb = bias[c];
        float sc = gam[c] * rsqrtf(rv[c] + EPSV);
        ss = sc;
        tt = beta[c] - rm[c] * sc;
    }
    dst[c] = bb; dst[DP + c] = ss; dst[2 * DP + c] = tt;
}

// ------------------------------------------------------------------
__device__ __forceinline__ uint32_t pack2h(float x, float y) {
    __half2 h = __floats2half2_rn(x, y);
    return *(uint32_t*)&h;
}

// W2 -> fp16, transposed [n][k] with stride WKS, zero-padded
__global__ void w_cvt_h_kernel(const float* __restrict__ W, __half* __restrict__ Wt) {
    int i = blockIdx.x * blockDim.x + threadIdx.x;
    if (i >= 136 * WKS) return;
    int n = i / WKS, k = i - n * WKS;
    float v = (k < D && n < D) ? __ldg(&W[k * D + n]) : 0.0f;
    Wt[i] = __float2half(v);
}

__device__ __forceinline__ void mma_f16(float* d,
                                        uint32_t a0, uint32_t a1, uint32_t a2, uint32_t a3,
                                        uint32_t b0, uint32_t b1) {
    asm volatile("mma.sync.aligned.m16n8k16.row.col.f32.f16.f16.f32 "
                 "{%0,%1,%2,%3}, {%4,%5,%6,%7}, {%8,%9}, {%0,%1,%2,%3};"
                 : "+f"(d[0]), "+f"(d[1]), "+f"(d[2]), "+f"(d[3])
                 : "r"(a0), "r"(a1), "r"(a2), "r"(a3), "r"(b0), "r"(b1));
}

// Tensor-core GEMM (fp16 m16n8k16): g_A16[row] = fp16( dinv[row] * (X @ W) ).
// W in smem fp16 transposed [n][k], stride WKS (bank-conflict-free B frags).
// n-split: warp pair shares 16 rows; colhalf 0 -> n-tiles 0..8, 1 -> 9..16.
// 9 k-steps of 16; tail step predicated against dmax.
template <bool CVT>
__global__ __launch_bounds__(256, 4)
void gemm_tc_kernel(const float* __restrict__ X, int ldx, int dmax,
                    const float* __restrict__ Wf, const __half* __restrict__ Wth) {
    extern __shared__ __half wsh[];          // [136 n][WKS k] fp16

    int tid  = threadIdx.x;
    int w    = tid >> 5;
    int lane = tid & 31;

    if (CVT) {
        // layer 1: convert + transpose W (f32 [k][n] row-major -> wsh[n][k])
        for (int idx = tid; idx < 72 * 136; idx += 256) {
            int kp = idx / 136;              // explicit div/mod (round-10 lesson)
            int n  = idx - kp * 136;
            int k  = 2 * kp;
            float f0 = (k < D     && n < D) ? __ldg(&Wf[k * D + n])       : 0.0f;
            float f1 = (k + 1 < D && n < D) ? __ldg(&Wf[(k + 1) * D + n]) : 0.0f;
            *(uint32_t*)&wsh[n * WKS + k] = pack2h(f0, f1);
        }
        // zero the k in [144, WKS) pad region (not covered by kp<72)
        for (int idx = tid; idx < 136 * (WKS - 144) / 2; idx += 256) {
            int n = idx / ((WKS - 144) / 2);
            int r = idx - n * ((WKS - 144) / 2);
            *(uint32_t*)&wsh[n * WKS + 144 + 2 * r] = 0u;
        }
    } else {
        const uint4* src = (const uint4*)Wth;
        uint4* dst = (uint4*)wsh;
#pragma unroll 4
        for (int i = tid; i < (136 * WKS) / 8; i += 256) dst[i] = __ldg(&src[i]);
    }
    __syncthreads();

    const int r0 = lane >> 2;        // A row group / B n
    const int kc = lane & 3;         // A k quad / B k
    const int colhalf = w & 1;
    const int ntBase = colhalf * 9;
    const int ntCnt  = 9 - colhalf;  // 9 or 8 tiles

    int rowbase = blockIdx.x * 64 + (w >> 1) * 16;
    int row0 = rowbase + r0;
    int row1 = row0 + 8;
    bool v0 = row0 < N_NODES;
    bool v1 = row1 < N_NODES;
    const float* X0 = X + (size_t)row0 * ldx;
    const float* X1 = X + (size_t)row1 * ldx;

    // per-thread B base (uint32 units); tile j: + j*(8*WKS/2); ks: + 8
    const uint32_t* wb = (const uint32_t*)&wsh[(ntBase * 8 + r0) * WKS + 2 * kc];

    float acc[9][4];
#pragma unroll
    for (int j = 0; j < 9; j++)
#pragma unroll
        for (int q = 0; q < 4; q++) acc[j][q] = 0.0f;

    // A frag for k-step ks: a0={X0[c],X0[c+1]}, a1={X1[c],X1[c+1]},
    // a2={X0[c+8],X0[c+9]}, a3={X1[c+8],X1[c+9]}, c = ks*16 + 2*kc.
    uint32_t a0, a1, a2, a3;
    {   // preload ks=0 (cols <= 15 < dmax)
        int c = 2 * kc;
        a0 = v0 ? pack2h(__ldg(X0 + c),     __ldg(X0 + c + 1)) : 0u;
        a1 = v1 ? pack2h(__ldg(X1 + c),     __ldg(X1 + c + 1)) : 0u;
        a2 = v0 ? pack2h(__ldg(X0 + c + 8), __ldg(X0 + c + 9)) : 0u;
        a3 = v1 ? pack2h(__ldg(X1 + c + 8), __ldg(X1 + c + 9)) : 0u;
    }

#pragma unroll
    for (int ks = 0; ks < 9; ks++) {
        uint32_t na0 = 0, na1 = 0, na2 = 0, na3 = 0;
        if (ks < 7) {                 // next step cols <= 127 < 133: no col pred
            int c = (ks + 1) * 16 + 2 * kc;
            na0 = v0 ? pack2h(__ldg(X0 + c),     __ldg(X0 + c + 1)) : 0u;
            na1 = v1 ? pack2h(__ldg(X1 + c),     __ldg(X1 + c + 1)) : 0u;
            na2 = v0 ? pack2h(__ldg(X0 + c + 8), __ldg(X0 + c + 9)) : 0u;
            na3 = v1 ? pack2h(__ldg(X1 + c + 8), __ldg(X1 + c + 9)) : 0u;
        } else if (ks == 7) {         // next = tail (cols 128..143): per-element pred
            int c = 128 + 2 * kc;
            float x0 = (v0 && c     < dmax) ? __ldg(X0 + c)     : 0.0f;
            float x1 = (v0 && c + 1 < dmax) ? __ldg(X0 + c + 1) : 0.0f;
            float y0 = (v1 && c     < dmax) ? __ldg(X1 + c)     : 0.0f;
            float y1 = (v1 && c + 1 < dmax) ? __ldg(X1 + c + 1) : 0.0f;
            float x2 = (v0 && c + 8 < dmax) ? __ldg(X0 + c + 8) : 0.0f;
            float x3 = (v0 && c + 9 < dmax) ? __ldg(X0 + c + 9) : 0.0f;
            float y2 = (v1 && c + 8 < dmax) ? __ldg(X1 + c + 8) : 0.0f;
            float y3 = (v1 && c + 9 < dmax) ? __ldg(X1 + c + 9) : 0.0f;
            na0 = pack2h(x0, x1); na1 = pack2h(y0, y1);
            na2 = pack2h(x2, x3); na3 = pack2h(y2, y3);
        }
#pragma unroll
        for (int j = 0; j < 9; j++) {
            if (j < ntCnt)
                mma_f16(acc[j], a0, a1, a2, a3,
                        wb[j * (4 * WKS) + ks * 8], wb[j * (4 * WKS) + ks * 8 + 4]);
        }
        a0 = na0; a1 = na1; a2 = na2; a3 = na3;
    }

    // epilogue: dinv scale -> fp16 half2 stores (cols 133..135 get 0 via W pads)
    float dv0 = v0 ? g_dinv[row0] : 0.0f;
    float dv1 = v1 ? g_dinv[row1] : 0.0f;
    int cb = 2 * kc;
#pragma unroll
    for (int j = 0; j < 9; j++) {
        if (j < ntCnt) {
            int c = (ntBase + j) * 8 + cb;
            if (v0)
                *(__half2*)(g_A16 + (size_t)row0 * DPH + c) =
                    __floats2half2_rn(dv0 * acc[j][0], dv0 * acc[j][1]);
            if (v1)
                *(__half2*)(g_A16 + (size_t)row1 * DPH + c) =
                    __floats2half2_rn(dv1 * acc[j][2], dv1 * acc[j][3]);
        }
    }
}

// ------------------------------------------------------------------
// Warp-per-node CSR gather, full-warp lanes: lane l accumulates cols 4l..4l+3
// (uint2 = 2 half2); lanes 0-1 also handle tail cols 128..135. fp32 accum.
__global__ __launch_bounds__(256)
void gather_post_kernel(const __half* __restrict__ A, float* __restrict__ Cout,
                        const float* __restrict__ post, int do_pool,
                        const int* __restrict__ batch) {
    int gw = (blockIdx.x * blockDim.x + threadIdx.x) >> 5;
    if (gw >= N_NODES) return;
    int lane = threadIdx.x & 31;
    int n = gw;

    int lo = __ldg(&g_off[n]);
    int hi = __ldg(&g_off[n + 1]);
    bool tl = lane < 2;

    float a0 = 0.f, a1 = 0.f, a2 = 0.f, a3 = 0.f;
    float t0 = 0.f, t1 = 0.f, t2 = 0.f, t3 = 0.f;

#define ACCUM(SJ) do {                                                        \
        const char* R = (const char*)(A + (size_t)(SJ) * DPH);                \
        uint2 m = __ldg((const uint2*)R + lane);                              \
        float2 f0 = __half22float2(*(const __half2*)&m.x);                    \
        float2 f1 = __half22float2(*(const __half2*)&m.y);                    \
        a0 += f0.x; a1 += f0.y; a2 += f1.x; a3 += f1.y;                       \
        if (tl) {                                                             \
            uint2 mt = __ldg((const uint2*)(R + 256) + lane);                 \
            float2 g0 = __half22float2(*(const __half2*)&mt.x);               \
            float2 g1 = __half22float2(*(const __half2*)&mt.y);               \
            t0 += g0.x; t1 += g0.y; t2 += g1.x; t3 += g1.y;                   \
        }                                                                     \
    } while (0)

    ACCUM(n);   // self-loop term

    int e = lo;
    for (; e + 32 <= hi; e += 32) {
        int src = __ldg(&g_csr[e + lane]);
#pragma unroll 4
        for (int j = 0; j < 32; j++) {
            int sj = __shfl_sync(0xffffffffu, src, j);
            ACCUM(sj);
        }
    }
    for (; e < hi; e++) {
        int sj = __ldg(&g_csr[e]);
        ACCUM(sj);
    }
#undef ACCUM

    float dv = __ldg(&g_dinv[n]);
    const float* bb = post;
    const float* ss = post + DP;
    const float* tt = post + 2 * DP;

    int c0 = 4 * lane;
    float4 o;
    o.x = fmaf(fmaxf(fmaf(dv, a0, __ldg(&bb[c0 + 0])), 0.f), __ldg(&ss[c0 + 0]), __ldg(&tt[c0 + 0]));
    o.y = fmaf(fmaxf(fmaf(dv, a1, __ldg(&bb[c0 + 1])), 0.f), __ldg(&ss[c0 + 1]), __ldg(&tt[c0 + 1]));
    o.z = fmaf(fmaxf(fmaf(dv, a2, __ldg(&bb[c0 + 2])), 0.f), __ldg(&ss[c0 + 2]), __ldg(&tt[c0 + 2]));
    o.w = fmaf(fmaxf(fmaf(dv, a3, __ldg(&bb[c0 + 3])), 0.f), __ldg(&ss[c0 + 3]), __ldg(&tt[c0 + 3]));
    float4 ot = make_float4(0.f, 0.f, 0.f, 0.f);
    if (tl) {
        int ct = 128 + 4 * lane;
        ot.x = fmaf(fmaxf(fmaf(dv, t0, __ldg(&bb[ct + 0])), 0.f), __ldg(&ss[ct + 0]), __ldg(&tt[ct + 0]));
        ot.y = fmaf(fmaxf(fmaf(dv, t1, __ldg(&bb[ct + 1])), 0.f), __ldg(&ss[ct + 1]), __ldg(&tt[ct + 1]));
        ot.z = fmaf(fmaxf(fmaf(dv, t2, __ldg(&bb[ct + 2])), 0.f), __ldg(&ss[ct + 2]), __ldg(&tt[ct + 2]));
        ot.w = fmaf(fmaxf(fmaf(dv, t3, __ldg(&bb[ct + 3])), 0.f), __ldg(&ss[ct + 3]), __ldg(&tt[ct + 3]));
    }

    if (!do_pool) {
        *(float4*)(Cout + (size_t)n * DP + c0) = o;
        if (tl) *(float4*)(Cout + (size_t)n * DP + 128 + 4 * lane) = ot;
    } else {
        int g = __ldg(&batch[n]);
        float* dst = g_P + (size_t)g * DP + c0;
        unsigned long long p0 = (unsigned long long)__cvta_generic_to_global(dst);
        asm volatile("red.global.add.v4.f32 [%0], {%1,%2,%3,%4};"
                     :: "l"(p0), "f"(o.x), "f"(o.y), "f"(o.z), "f"(o.w) : "memory");
        if (tl) {
            float* dt = g_P + (size_t)g * DP + 128 + 4 * lane;
            unsigned long long p1 = (unsigned long long)__cvta_generic_to_global(dt);
            asm volatile("red.global.add.v4.f32 [%0], {%1,%2,%3,%4};"
                         :: "l"(p1), "f"(ot.x), "f"(ot.y), "f"(ot.z), "f"(ot.w) : "memory");
        }
    }
}

// ------------------------------------------------------------------
__device__ __forceinline__ int lbound(const int* b, int n, int v) {
    int lo = 0, hi = n;
    while (lo < hi) { int m = (lo + hi) >> 1; if (b[m] < v) lo = m + 1; else hi = m; }
    return lo;
}

__global__ void cntg_kernel(const int* __restrict__ batch) {
    int g = blockIdx.x * blockDim.x + threadIdx.x;
    if (g < N_GRAPHS)
        g_cntg[g] = lbound(batch, N_NODES, g + 1) - lbound(batch, N_NODES, g);
}

__global__ void divide_kernel(float* __restrict__ out) {
    int idx = blockIdx.x * blockDim.x + threadIdx.x;
    if (idx >= N_GRAPHS * D) return;
    int g = idx / D;
    int c = idx - g * D;
    float cnt = (float)g_cntg[g];
    out[idx] = g_P[(size_t)g * DP + c] / fmaxf(cnt, 1.0f);
}

// ------------------------------------------------------------------
extern "C" void kernel_launch(void* const* d_in, const int* in_sizes, int n_in,
                              void* d_out, int out_size) {
    const float* x     = (const float*)d_in[0];
    const int*   ei    = (const int*)d_in[1];
    const int*   batch = (const int*)d_in[2];
    const float* W1  = (const float*)d_in[3];
    const float* b1  = (const float*)d_in[4];
    const float* W2  = (const float*)d_in[5];
    const float* b2  = (const float*)d_in[6];
    const float* g1  = (const float*)d_in[7];
    const float* be1 = (const float*)d_in[8];
    const float* rm1 = (const float*)d_in[9];
    const float* rv1 = (const float*)d_in[10];
    const float* g2  = (const float*)d_in[11];
    const float* be2 = (const float*)d_in[12];
    const float* rm2 = (const float*)d_in[13];
    const float* rv2 = (const float*)d_in[14];
    float* out = (float*)d_out;

    __half *pA, *pW2th;
    float *pC, *pP1, *pP2;
    cudaGetSymbolAddress((void**)&pA, g_A16);
    cudaGetSymbolAddress((void**)&pC, g_C);
    cudaGetSymbolAddress((void**)&pP1, g_post1);
    cudaGetSymbolAddress((void**)&pP2, g_post2);
    cudaGetSymbolAddress((void**)&pW2th, g_W2th);

    // side stream + fork/join events, created once (no device allocation)
    static cudaStream_t s_side = nullptr;
    static cudaEvent_t ev_fork = nullptr, ev_join = nullptr;
    if (!s_side) {
        cudaStreamCreateWithFlags(&s_side, cudaStreamNonBlocking);
        cudaEventCreateWithFlags(&ev_fork, cudaEventDisableTiming);
        cudaEventCreateWithFlags(&ev_join, cudaEventDisableTiming);
    }

    const int smem = 136 * WKS * (int)sizeof(__half);           // 41.3 KB
    cudaFuncSetAttribute((const void*)gemm_tc_kernel<true>,
                         cudaFuncAttributeMaxDynamicSharedMemorySize, smem);
    cudaFuncSetAttribute((const void*)gemm_tc_kernel<false>,
                         cudaFuncAttributeMaxDynamicSharedMemorySize, smem);

    const int TB = 256;
    const int gemm_blocks   = (N_NODES + 63) / 64;                // 782
    const int gather_blocks = (N_NODES * 32 + TB - 1) / TB;       // warp per node

    // ---- main: zero(1), count(2), dinv(3), gemm1(4) -> ncu captures gemm1 ----
    zero_fused_kernel<<<(N_GRAPHS * DP + TB - 1) / TB, TB>>>();
    count_deg_kernel<<<(N_EDGES + TB - 1) / TB, TB>>>(ei);
    cudaEventRecord(ev_fork, 0);
    dinv_kernel<<<(N_NODES + TB - 1) / TB, TB>>>();
    gemm_tc_kernel<true><<<gemm_blocks, TB, smem>>>(x, D, D, W1, nullptr);

    // ---- side: CSR build + misc, overlapped with gemm1 ----
    cudaStreamWaitEvent(s_side, ev_fork, 0);
    scan1_kernel<<<SCAN_NB, SCAN_B, 0, s_side>>>();
    scan2_kernel<<<1, 32, 0, s_side>>>();
    scan3_kernel<<<SCAN_NB, SCAN_B, 0, s_side>>>();
    fill_csr_kernel<<<(N_EDGES + TB - 1) / TB, TB, 0, s_side>>>(ei);
    w_cvt_h_kernel<<<(136 * WKS + TB - 1) / TB, TB, 0, s_side>>>(W2, pW2th);
    prep_post_kernel<<<1, DP, 0, s_side>>>(b1, g1, be1, rm1, rv1, pP1);
    prep_post_kernel<<<1, DP, 0, s_side>>>(b2, g2, be2, rm2, rv2, pP2);
    cntg_kernel<<<(N_GRAPHS + TB - 1) / TB, TB, 0, s_side>>>(batch);
    cudaEventRecord(ev_join, s_side);

    // ---- join, then the serial tail ----
    cudaStreamWaitEvent(0, ev_join, 0);
    gather_post_kernel<<<gather_blocks, TB>>>(pA, pC, pP1, 0, batch);
    gemm_tc_kernel<false><<<gemm_blocks, TB, smem>>>(pC, DP, DP, nullptr, pW2th);
    gather_post_kernel<<<gather_blocks, TB>>>(pA, pC, pP2, 1, batch);
    divide_kernel<<<(N_GRAPHS * D + TB - 1) / TB, TB>>>(out);
}

// round 13
// speedup vs baseline: 1.2472x; 1.0198x over previous
#include <cuda_runtime.h>
#include <cuda_fp16.h>
#include <cstdint>

#define N_NODES 50000
#define N_EDGES 1600000
#define N_GRAPHS 2048
#define D 133
#define DP 136           // fp32 padded row (floats)
#define DPH 144          // fp16 padded row (halves) = 288B (9 sectors)
#define WKS 152          // W smem k-stride in halves (bank-conflict-free)
#define EPSV 1e-5f
#define SCAN_B 1024
#define SCAN_NB ((N_NODES + SCAN_B - 1) / SCAN_B)   // 49

// -------- scratch (static device globals; no runtime allocation) --------
__device__ __align__(16) __half g_A16[(size_t)N_NODES * DPH];  // gemm out (messages)
__device__ __align__(16) __half g_X16[(size_t)N_NODES * DPH];  // gemm in (X or layer-1 out)
__device__ __align__(16) float  g_P[(size_t)N_GRAPHS * DP];    // pool accumulator
__device__ __align__(16) __half g_W2th[136 * WKS];             // W2 fp16, [n][k] transposed
__device__ float g_dinv[N_NODES];
__device__ int   g_cnt[N_NODES];
__device__ int   g_off[N_NODES + 1];
__device__ int   g_cursor[N_NODES];
__device__ int   g_csr[N_EDGES];
__device__ int   g_bsum[SCAN_NB];
__device__ int   g_cntg[N_GRAPHS];
__device__ float g_post1[3 * DP];    // bias | s | t   (zero-padded)
__device__ float g_post2[3 * DP];

// ------------------------------------------------------------------
__global__ void zero_fused_kernel() {
    int i = blockIdx.x * blockDim.x + threadIdx.x;
    if (i < N_GRAPHS * DP) g_P[i] = 0.0f;
    if (i < N_NODES)       g_cnt[i] = 0;
}

__global__ void count_deg_kernel(const int* __restrict__ ei) {
    int e = blockIdx.x * blockDim.x + threadIdx.x;
    if (e < N_EDGES) atomicAdd(&g_cnt[__ldg(&ei[N_EDGES + e])], 1);
}

__device__ __forceinline__ uint32_t pack2h(float x, float y) {
    __half2 h = __floats2half2_rn(x, y);
    return *(uint32_t*)&h;
}

// fused: X (fp32 [N,133]) -> g_X16 (fp16 [N,144], pads 0), and dinv.
// thread idx: row = idx/36, q = idx%36 covers cols 4q..4q+3 as one uint2.
__global__ void prep_x_dinv_kernel(const float* __restrict__ X) {
    int idx = blockIdx.x * blockDim.x + threadIdx.x;
    if (idx < N_NODES) g_dinv[idx] = rsqrtf((float)(g_cnt[idx] + 1));
    if (idx >= N_NODES * 36) return;
    int row = idx / 36;
    int q   = idx - row * 36;
    int c   = 4 * q;
    const float* Xr = X + (size_t)row * D;
    float f0 = (c     < D) ? __ldg(Xr + c)     : 0.0f;
    float f1 = (c + 1 < D) ? __ldg(Xr + c + 1) : 0.0f;
    float f2 = (c + 2 < D) ? __ldg(Xr + c + 2) : 0.0f;
    float f3 = (c + 3 < D) ? __ldg(Xr + c + 3) : 0.0f;
    uint2 o = make_uint2(pack2h(f0, f1), pack2h(f2, f3));
    ((uint2*)(g_X16 + (size_t)row * DPH))[q] = o;
}

// ---- 3-kernel exclusive scan of g_cnt -> g_off ----
__global__ void scan1_kernel() {
    __shared__ int sh[SCAN_B];
    int t = threadIdx.x;
    int i = blockIdx.x * SCAN_B + t;
    int v = (i < N_NODES) ? g_cnt[i] : 0;
    sh[t] = v;
    __syncthreads();
#pragma unroll
    for (int d = 1; d < SCAN_B; d <<= 1) {
        int x = (t >= d) ? sh[t - d] : 0;
        __syncthreads();
        sh[t] += x;
        __syncthreads();
    }
    if (i < N_NODES) g_off[i] = sh[t] - v;           // exclusive, local
    if (t == SCAN_B - 1) g_bsum[blockIdx.x] = sh[t];
}

__global__ void scan2_kernel() {
    if (threadIdx.x == 0) {
        int acc = 0;
        for (int b = 0; b < SCAN_NB; b++) {
            int v = g_bsum[b];
            g_bsum[b] = acc;
            acc += v;
        }
    }
}

__global__ void scan3_kernel() {
    int i = blockIdx.x * blockDim.x + threadIdx.x;
    if (i < N_NODES) {
        int o = g_off[i] + g_bsum[i / SCAN_B];
        g_off[i] = o;
        g_cursor[i] = o;
    }
    if (i == 0) g_off[N_NODES] = N_EDGES;
}

__global__ void fill_csr_kernel(const int* __restrict__ ei) {
    int e = blockIdx.x * blockDim.x + threadIdx.x;
    if (e < N_EDGES) {
        int r = __ldg(&ei[e]);
        int c = __ldg(&ei[N_EDGES + e]);
        int pos = atomicAdd(&g_cursor[c], 1);
        g_csr[pos] = r;
    }
}

// ---- per-layer fused BN constants: bias | s | t, zero-padded to DP ----
__global__ void prep_post_kernel(const float* __restrict__ bias, const float* __restrict__ gam,
                                 const float* __restrict__ beta, const float* __restrict__ rm,
                                 const float* __restrict__ rv, float* __restrict__ dst) {
    int c = threadIdx.x;
    if (c >= DP) return;
    float bb = 0.0f, ss = 0.0f, tt = 0.0f;
    if (c < D) {
        bb = bias[c];
        float sc = gam[c] * rsqrtf(rv[c] + EPSV);
        ss = sc;
        tt = beta[c] - rm[c] * sc;
    }
    dst[c] = bb; dst[DP + c] = ss; dst[2 * DP + c] = tt;
}

// W2 -> fp16, transposed [n][k] with stride WKS, zero-padded
__global__ void w_cvt_h_kernel(const float* __restrict__ W, __half* __restrict__ Wt) {
    int i = blockIdx.x * blockDim.x + threadIdx.x;
    if (i >= 136 * WKS) return;
    int n = i / WKS, k = i - n * WKS;
    float v = (k < D && n < D) ? __ldg(&W[k * D + n]) : 0.0f;
    Wt[i] = __float2half(v);
}

__device__ __forceinline__ void mma_f16(float* d,
                                        uint32_t a0, uint32_t a1, uint32_t a2, uint32_t a3,
                                        uint32_t b0, uint32_t b1) {
    asm volatile("mma.sync.aligned.m16n8k16.row.col.f32.f16.f16.f32 "
                 "{%0,%1,%2,%3}, {%4,%5,%6,%7}, {%8,%9}, {%0,%1,%2,%3};"
                 : "+f"(d[0]), "+f"(d[1]), "+f"(d[2]), "+f"(d[3])
                 : "r"(a0), "r"(a1), "r"(a2), "r"(a3), "r"(b0), "r"(b1));
}

// Tensor-core GEMM (fp16 m16n8k16): g_A16[row] = fp16( dinv[row] * (Xh @ W) ).
// A input fp16 [N, DPH] with zeroed pads -> 4 packed LDG.32 per k-step, no cvt.
// W in smem fp16 transposed [n][k], stride WKS. n-split across warp pairs.
template <bool CVT>
__global__ __launch_bounds__(256, 4)
void gemm_tc_kernel(const __half* __restrict__ Xh,
                    const float* __restrict__ Wf, const __half* __restrict__ Wth) {
    extern __shared__ __half wsh[];          // [136 n][WKS k] fp16

    int tid  = threadIdx.x;
    int w    = tid >> 5;
    int lane = tid & 31;

    if (CVT) {
        // layer 1: convert + transpose W (f32 [k][n] row-major -> wsh[n][k])
        for (int idx = tid; idx < 72 * 136; idx += 256) {
            int kp = idx / 136;
            int n  = idx - kp * 136;
            int k  = 2 * kp;
            float f0 = (k < D     && n < D) ? __ldg(&Wf[k * D + n])       : 0.0f;
            float f1 = (k + 1 < D && n < D) ? __ldg(&Wf[(k + 1) * D + n]) : 0.0f;
            *(uint32_t*)&wsh[n * WKS + k] = pack2h(f0, f1);
        }
        // zero the k in [144, WKS) pad region
        for (int idx = tid; idx < 136 * (WKS - 144) / 2; idx += 256) {
            int n = idx / ((WKS - 144) / 2);
            int r = idx - n * ((WKS - 144) / 2);
            *(uint32_t*)&wsh[n * WKS + 144 + 2 * r] = 0u;
        }
    } else {
        const uint4* src = (const uint4*)Wth;
        uint4* dst = (uint4*)wsh;
#pragma unroll 4
        for (int i = tid; i < (136 * WKS) / 8; i += 256) dst[i] = __ldg(&src[i]);
    }
    __syncthreads();

    const int r0 = lane >> 2;        // A row group / B n
    const int kc = lane & 3;         // A k quad / B k
    const int colhalf = w & 1;
    const int ntBase = colhalf * 9;
    const int ntCnt  = 9 - colhalf;  // 9 or 8 tiles

    int rowbase = blockIdx.x * 64 + (w >> 1) * 16;
    int row0 = rowbase + r0;
    int row1 = row0 + 8;
    bool v0 = row0 < N_NODES;
    bool v1 = row1 < N_NODES;
    const uint32_t* x0p = (const uint32_t*)(Xh + (size_t)(v0 ? row0 : 0) * DPH);
    const uint32_t* x1p = (const uint32_t*)(Xh + (size_t)(v1 ? row1 : 0) * DPH);

    // per-thread B base (uint32 units); tile j: + j*(4*WKS); ks: + 8
    const uint32_t* wb = (const uint32_t*)&wsh[(ntBase * 8 + r0) * WKS + 2 * kc];

    float acc[9][4];
#pragma unroll
    for (int j = 0; j < 9; j++)
#pragma unroll
        for (int q = 0; q < 4; q++) acc[j][q] = 0.0f;

    // A frag for k-step ks (packed half2 words): word index ks*8 + kc (+4)
    uint32_t a0 = __ldg(x0p + kc);
    uint32_t a1 = __ldg(x1p + kc);
    uint32_t a2 = __ldg(x0p + kc + 4);
    uint32_t a3 = __ldg(x1p + kc + 4);

#pragma unroll
    for (int ks = 0; ks < 9; ks++) {
        uint32_t na0 = 0, na1 = 0, na2 = 0, na3 = 0;
        if (ks < 8) {
            int wi = (ks + 1) * 8 + kc;
            na0 = __ldg(x0p + wi);
            na1 = __ldg(x1p + wi);
            na2 = __ldg(x0p + wi + 4);
            na3 = __ldg(x1p + wi + 4);
        }
#pragma unroll
        for (int j = 0; j < 9; j++) {
            if (j < ntCnt)
                mma_f16(acc[j], a0, a1, a2, a3,
                        wb[j * (4 * WKS) + ks * 8], wb[j * (4 * WKS) + ks * 8 + 4]);
        }
        a0 = na0; a1 = na1; a2 = na2; a3 = na3;
    }

    // epilogue: dinv scale -> fp16 half2 stores (cols 133..135 get 0 via W pads)
    float dv0 = v0 ? g_dinv[row0] : 0.0f;
    float dv1 = v1 ? g_dinv[row1] : 0.0f;
    int cb = 2 * kc;
#pragma unroll
    for (int j = 0; j < 9; j++) {
        if (j < ntCnt) {
            int c = (ntBase + j) * 8 + cb;
            if (v0)
                *(__half2*)(g_A16 + (size_t)row0 * DPH + c) =
                    __floats2half2_rn(dv0 * acc[j][0], dv0 * acc[j][1]);
            if (v1)
                *(__half2*)(g_A16 + (size_t)row1 * DPH + c) =
                    __floats2half2_rn(dv1 * acc[j][2], dv1 * acc[j][3]);
        }
    }
}

// ------------------------------------------------------------------
// Warp-per-node CSR gather, full-warp lanes: lane l accumulates cols 4l..4l+3
// (uint2 = 2 half2); lanes 0-1 also handle tail cols 128..135. fp32 accum.
// POOL=0: write fp16 row (DPH, pads zeroed) to g_X16 for the next GEMM.
// POOL=1: red.v4 fp32 into g_P[batch[n]].
template <int POOL>
__global__ __launch_bounds__(256)
void gather_post_kernel(const __half* __restrict__ A,
                        const float* __restrict__ post,
                        const int* __restrict__ batch) {
    int gw = (blockIdx.x * blockDim.x + threadIdx.x) >> 5;
    if (gw >= N_NODES) return;
    int lane = threadIdx.x & 31;
    int n = gw;

    int lo = __ldg(&g_off[n]);
    int hi = __ldg(&g_off[n + 1]);
    bool tl = lane < 2;

    float a0 = 0.f, a1 = 0.f, a2 = 0.f, a3 = 0.f;
    float t0 = 0.f, t1 = 0.f, t2 = 0.f, t3 = 0.f;

#define ACCUM(SJ) do {                                                        \
        const char* R = (const char*)(A + (size_t)(SJ) * DPH);                \
        uint2 m = __ldg((const uint2*)R + lane);                              \
        float2 f0 = __half22float2(*(const __half2*)&m.x);                    \
        float2 f1 = __half22float2(*(const __half2*)&m.y);                    \
        a0 += f0.x; a1 += f0.y; a2 += f1.x; a3 += f1.y;                       \
        if (tl) {                                                             \
            uint2 mt = __ldg((const uint2*)(R + 256) + lane);                 \
            float2 g0 = __half22float2(*(const __half2*)&mt.x);               \
            float2 g1 = __half22float2(*(const __half2*)&mt.y);               \
            t0 += g0.x; t1 += g0.y; t2 += g1.x; t3 += g1.y;                   \
        }                                                                     \
    } while (0)

    ACCUM(n);   // self-loop term

    int e = lo;
    for (; e + 32 <= hi; e += 32) {
        int src = __ldg(&g_csr[e + lane]);
#pragma unroll 4
        for (int j = 0; j < 32; j++) {
            int sj = __shfl_sync(0xffffffffu, src, j);
            ACCUM(sj);
        }
    }
    for (; e < hi; e++) {
        int sj = __ldg(&g_csr[e]);
        ACCUM(sj);
    }
#undef ACCUM

    float dv = __ldg(&g_dinv[n]);
    const float* bb = post;
    const float* ss = post + DP;
    const float* tt = post + 2 * DP;

    int c0 = 4 * lane;
    float4 o;
    o.x = fmaf(fmaxf(fmaf(dv, a0, __ldg(&bb[c0 + 0])), 0.f), __ldg(&ss[c0 + 0]), __ldg(&tt[c0 + 0]));
    o.y = fmaf(fmaxf(fmaf(dv, a1, __ldg(&bb[c0 + 1])), 0.f), __ldg(&ss[c0 + 1]), __ldg(&tt[c0 + 1]));
    o.z = fmaf(fmaxf(fmaf(dv, a2, __ldg(&bb[c0 + 2])), 0.f), __ldg(&ss[c0 + 2]), __ldg(&tt[c0 + 2]));
    o.w = fmaf(fmaxf(fmaf(dv, a3, __ldg(&bb[c0 + 3])), 0.f), __ldg(&ss[c0 + 3]), __ldg(&tt[c0 + 3]));
    float4 ot = make_float4(0.f, 0.f, 0.f, 0.f);
    if (tl) {
        int ct = 128 + 4 * lane;
        ot.x = fmaf(fmaxf(fmaf(dv, t0, __ldg(&bb[ct + 0])), 0.f), __ldg(&ss[ct + 0]), __ldg(&tt[ct + 0]));
        ot.y = fmaf(fmaxf(fmaf(dv, t1, __ldg(&bb[ct + 1])), 0.f), __ldg(&ss[ct + 1]), __ldg(&tt[ct + 1]));
        ot.z = fmaf(fmaxf(fmaf(dv, t2, __ldg(&bb[ct + 2])), 0.f), __ldg(&ss[ct + 2]), __ldg(&tt[ct + 2]));
        ot.w = fmaf(fmaxf(fmaf(dv, t3, __ldg(&bb[ct + 3])), 0.f), __ldg(&ss[ct + 3]), __ldg(&tt[ct + 3]));
    }

    if (POOL == 0) {
        // fp16 output row for next GEMM (cols 133..135 of ot are 0: BN consts padded 0)
        uint2* Cr = (uint2*)(g_X16 + (size_t)n * DPH);
        Cr[lane] = make_uint2(pack2h(o.x, o.y), pack2h(o.z, o.w));
        if (tl) Cr[32 + lane] = make_uint2(pack2h(ot.x, ot.y), pack2h(ot.z, ot.w));
        if (lane == 2)   // zero pads cols 136..143
            *(uint4*)(g_X16 + (size_t)n * DPH + 136) = make_uint4(0, 0, 0, 0);
    } else {
        int g = __ldg(&batch[n]);
        float* dst = g_P + (size_t)g * DP + c0;
        unsigned long long p0 = (unsigned long long)__cvta_generic_to_global(dst);
        asm volatile("red.global.add.v4.f32 [%0], {%1,%2,%3,%4};"
                     :: "l"(p0), "f"(o.x), "f"(o.y), "f"(o.z), "f"(o.w) : "memory");
        if (tl) {
            float* dt = g_P + (size_t)g * DP + 128 + 4 * lane;
            unsigned long long p1 = (unsigned long long)__cvta_generic_to_global(dt);
            asm volatile("red.global.add.v4.f32 [%0], {%1,%2,%3,%4};"
                         :: "l"(p1), "f"(ot.x), "f"(ot.y), "f"(ot.z), "f"(ot.w) : "memory");
        }
    }
}

// ------------------------------------------------------------------
__device__ __forceinline__ int lbound(const int* b, int n, int v) {
    int lo = 0, hi = n;
    while (lo < hi) { int m = (lo + hi) >> 1; if (b[m] < v) lo = m + 1; else hi = m; }
    return lo;
}

__global__ void cntg_kernel(const int* __restrict__ batch) {
    int g = blockIdx.x * blockDim.x + threadIdx.x;
    if (g < N_GRAPHS)
        g_cntg[g] = lbound(batch, N_NODES, g + 1) - lbound(batch, N_NODES, g);
}

__global__ void divide_kernel(float* __restrict__ out) {
    int idx = blockIdx.x * blockDim.x + threadIdx.x;
    if (idx >= N_GRAPHS * D) return;
    int g = idx / D;
    int c = idx - g * D;
    float cnt = (float)g_cntg[g];
    out[idx] = g_P[(size_t)g * DP + c] / fmaxf(cnt, 1.0f);
}

// ------------------------------------------------------------------
extern "C" void kernel_launch(void* const* d_in, const int* in_sizes, int n_in,
                              void* d_out, int out_size) {
    const float* x     = (const float*)d_in[0];
    const int*   ei    = (const int*)d_in[1];
    const int*   batch = (const int*)d_in[2];
    const float* W1  = (const float*)d_in[3];
    const float* b1  = (const float*)d_in[4];
    const float* W2  = (const float*)d_in[5];
    const float* b2  = (const float*)d_in[6];
    const float* g1  = (const float*)d_in[7];
    const float* be1 = (const float*)d_in[8];
    const float* rm1 = (const float*)d_in[9];
    const float* rv1 = (const float*)d_in[10];
    const float* g2  = (const float*)d_in[11];
    const float* be2 = (const float*)d_in[12];
    const float* rm2 = (const float*)d_in[13];
    const float* rv2 = (const float*)d_in[14];
    float* out = (float*)d_out;

    __half *pA, *pX, *pW2th;
    float *pP1, *pP2;
    cudaGetSymbolAddress((void**)&pA, g_A16);
    cudaGetSymbolAddress((void**)&pX, g_X16);
    cudaGetSymbolAddress((void**)&pP1, g_post1);
    cudaGetSymbolAddress((void**)&pP2, g_post2);
    cudaGetSymbolAddress((void**)&pW2th, g_W2th);

    // side stream + fork/join events, created once (no device allocation)
    static cudaStream_t s_side = nullptr;
    static cudaEvent_t ev_fork = nullptr, ev_join = nullptr;
    if (!s_side) {
        cudaStreamCreateWithFlags(&s_side, cudaStreamNonBlocking);
        cudaEventCreateWithFlags(&ev_fork, cudaEventDisableTiming);
        cudaEventCreateWithFlags(&ev_join, cudaEventDisableTiming);
    }

    const int smem = 136 * WKS * (int)sizeof(__half);           // 41.3 KB
    cudaFuncSetAttribute((const void*)gemm_tc_kernel<true>,
                         cudaFuncAttributeMaxDynamicSharedMemorySize, smem);
    cudaFuncSetAttribute((const void*)gemm_tc_kernel<false>,
                         cudaFuncAttributeMaxDynamicSharedMemorySize, smem);

    const int TB = 256;
    const int gemm_blocks   = (N_NODES + 63) / 64;                // 782
    const int gather_blocks = (N_NODES * 32 + TB - 1) / TB;       // warp per node

    // ---- main: zero(1), count(2), prep_x+dinv(3), gemm1(4) -> ncu sees gemm1 ----
    zero_fused_kernel<<<(N_GRAPHS * DP + TB - 1) / TB, TB>>>();
    count_deg_kernel<<<(N_EDGES + TB - 1) / TB, TB>>>(ei);
    cudaEventRecord(ev_fork, 0);
    prep_x_dinv_kernel<<<(N_NODES * 36 + TB - 1) / TB, TB>>>(x);
    gemm_tc_kernel<true><<<gemm_blocks, TB, smem>>>(pX, W1, nullptr);

    // ---- side: CSR build + misc, overlapped with gemm1 ----
    cudaStreamWaitEvent(s_side, ev_fork, 0);
    scan1_kernel<<<SCAN_NB, SCAN_B, 0, s_side>>>();
    scan2_kernel<<<1, 32, 0, s_side>>>();
    scan3_kernel<<<SCAN_NB, SCAN_B, 0, s_side>>>();
    fill_csr_kernel<<<(N_EDGES + TB - 1) / TB, TB, 0, s_side>>>(ei);
    w_cvt_h_kernel<<<(136 * WKS + TB - 1) / TB, TB, 0, s_side>>>(W2, pW2th);
    prep_post_kernel<<<1, DP, 0, s_side>>>(b1, g1, be1, rm1, rv1, pP1);
    prep_post_kernel<<<1, DP, 0, s_side>>>(b2, g2, be2, rm2, rv2, pP2);
    cntg_kernel<<<(N_GRAPHS + TB - 1) / TB, TB, 0, s_side>>>(batch);
    cudaEventRecord(ev_join, s_side);

    // ---- join, then the serial tail ----
    cudaStreamWaitEvent(0, ev_join, 0);
    gather_post_kernel<0><<<gather_blocks, TB>>>(pA, pP1, batch);   // -> g_X16
    gemm_tc_kernel<false><<<gemm_blocks, TB, smem>>>(pX, nullptr, pW2th);
    gather_post_kernel<1><<<gather_blocks, TB>>>(pA, pP2, batch);   // -> g_P
    divide_kernel<<<(N_GRAPHS * D + TB - 1) / TB, TB>>>(out);
}